// round 9
// baseline (speedup 1.0000x reference)
#include <cuda_runtime.h>
#include <math.h>
#include <stdint.h>

#define S_IMG 2048
#define S_TXT 512
#define S_TOT 2560
#define DM    3072
#define NH    24
#define HD    128
#define ATOK  4
#define ADIM  1024
#define SM_SCALE 0.08838834764831845f  /* 1/sqrt(128) */

// ---------------- scratch (device globals; no allocation allowed) ----------------
__device__ float g_pq_img[(size_t)S_IMG * DM];
__device__ float g_pk_img[(size_t)S_IMG * DM];
__device__ float g_pv_img[(size_t)S_IMG * DM];
__device__ float g_pq_txt[(size_t)S_TXT * DM];
__device__ float g_pk_txt[(size_t)S_TXT * DM];
__device__ float g_pv_txt[(size_t)S_TXT * DM];
__device__ float g_q[(size_t)NH * S_TOT * HD];
__device__ float g_k[(size_t)NH * S_TOT * HD];
__device__ float g_v[(size_t)NH * S_TOT * HD];
__device__ float g_o[(size_t)NH * S_TOT * HD];
__device__ float g_hs[(size_t)S_TOT * DM];
__device__ float g_ka[ATOK * DM];
__device__ float g_va[ATOK * DM];
// tf32-pre-rounded copies (exact-truncation path for mma)
__device__ float g_chid[(size_t)S_IMG * DM];
__device__ float g_cenc[(size_t)S_TXT * DM];
__device__ float g_cad[ATOK * ADIM];
__device__ float g_cWq[(size_t)DM * DM];
__device__ float g_cWk[(size_t)DM * DM];
__device__ float g_cWv[(size_t)DM * DM];
__device__ float g_cWqa[(size_t)DM * DM];
__device__ float g_cWka[(size_t)DM * DM];
__device__ float g_cWva[(size_t)DM * DM];
__device__ float g_cWo[(size_t)DM * DM];
__device__ float g_cWoa[(size_t)DM * DM];
__device__ float g_cWkad[(size_t)ADIM * DM];
__device__ float g_cWvad[(size_t)ADIM * DM];

// ------------------------- helpers ----------------------------------------------
__device__ __forceinline__ uint32_t f2tf32(float f) {
    uint32_t r;
    asm("cvt.rna.tf32.f32 %0, %1;" : "=r"(r) : "f"(f));
    return r;
}
__device__ __forceinline__ float tf32r(float f) { return __uint_as_float(f2tf32(f)); }
__device__ __forceinline__ float4 cvt4(float4 v) {
    return make_float4(tf32r(v.x), tf32r(v.y), tf32r(v.z), tf32r(v.w));
}
__device__ __forceinline__ void mma_tf32(float4& d, const uint32_t a[4],
                                         const uint32_t b[2]) {
    asm volatile(
        "mma.sync.aligned.m16n8k8.row.col.f32.tf32.tf32.f32 "
        "{%0,%1,%2,%3}, {%4,%5,%6,%7}, {%8,%9}, {%0,%1,%2,%3};\n"
        : "+f"(d.x), "+f"(d.y), "+f"(d.z), "+f"(d.w)
        : "r"(a[0]), "r"(a[1]), "r"(a[2]), "r"(a[3]), "r"(b[0]), "r"(b[1]));
}
#define CPA16(dst, src, pb) \
    asm volatile("cp.async.cg.shared.global [%0], [%1], 16, %2;\n" \
                 :: "r"(dst), "l"(src), "r"(pb))
#define CPCOMMIT() asm volatile("cp.async.commit_group;\n" ::)
#define CPWAIT(n)  asm volatile("cp.async.wait_group %0;\n" :: "n"(n))

// ------------------------- pre-round pass ----------------------------------------
struct CV { const float* s; float* d; int n; };
struct CV13 { CV e[13]; };
__global__ __launch_bounds__(256) void prep_cvt(CV13 t)
{
    const CV c = t.e[blockIdx.y];
    int idx = (blockIdx.x * 256 + threadIdx.x) * 4;
    if (idx < c.n)
        *(float4*)&c.d[idx] = cvt4(*(const float4*)&c.s[idx]);
}

// --------- batched cp.async tf32 GEMM: C = A[M,K] @ W[K,3072] + bias -------------
// CTA tile 128x256, warp tile 64x64 (8 warps, 2x4), BK=16, 4-stage pipeline.
#define BM 128
#define BN 256
#define BKG 16
#define PA 20     /* 20 mod 32 = 4: A-frag banks bijective */
#define PB 264    /* 264 mod 32 = 8: B-frag banks bijective */
#define GSTAGE (BM * PA + BKG * PB)        /* 6784 floats per stage */
#define GSMEM  (4 * GSTAGE * 4)            /* 108544 B */

struct GB { const float* A; const float* W; const float* bias; float* C; int M; int K; };
struct GB6 { GB e[6]; };

__global__ __launch_bounds__(256, 1) void gemm_ca(GB6 ga)
{
    const GB g = ga.e[blockIdx.z];
    const int M = g.M, K = g.K;
    const int m0 = blockIdx.y * BM;
    if (m0 >= M) return;
    const int n0 = blockIdx.x * BN;

    extern __shared__ float smg[];
    const float* __restrict__ A = g.A;
    const float* __restrict__ W = g.W;
    const int tid  = threadIdx.x;
    const int warp = tid >> 5, lane = tid & 31;
    const int gid  = lane >> 2, tig = lane & 3;
    const int wm = (warp >> 2) * 64;   // 2 m-warps
    const int wn = (warp & 3) * 64;    // 4 n-warps

    const int nIters = K / BKG;

    auto issue_tile = [&](int it, int stage) {
        float* As = smg + stage * GSTAGE;
        float* Bs = As + BM * PA;
        const int k0 = it * BKG;
        // A tile: 128 rows x 16 k = 512 16B-chunks, 2/thread
        #pragma unroll
        for (int i = 0; i < 2; i++) {
            int c = tid + i * 256;
            int r = c >> 2, col = (c & 3) * 4;
            uint32_t dst = (uint32_t)__cvta_generic_to_shared(&As[r * PA + col]);
            const float* src = &A[(size_t)(m0 + r) * K + k0 + col];
            CPA16(dst, src, (m0 + r < M) ? 16 : 0);
        }
        // B tile: 16 rows x 256 n = 1024 chunks, 4/thread
        #pragma unroll
        for (int i = 0; i < 4; i++) {
            int c = tid + i * 256;
            int r = c >> 6, col = (c & 63) * 4;
            uint32_t dst = (uint32_t)__cvta_generic_to_shared(&Bs[r * PB + col]);
            const float* src = &W[(size_t)(k0 + r) * DM + n0 + col];
            CPA16(dst, src, 16);
        }
        CPCOMMIT();
    };

    float4 acc[4][8];
    #pragma unroll
    for (int i = 0; i < 4; i++)
        #pragma unroll
        for (int j = 0; j < 8; j++) acc[i][j] = make_float4(0.f, 0.f, 0.f, 0.f);

    #pragma unroll
    for (int i = 0; i < 3; i++) {
        if (i < nIters) issue_tile(i, i); else CPCOMMIT();
    }

    for (int it = 0; it < nIters; it++) {
        CPWAIT(2);
        __syncthreads();
        if (it + 3 < nIters) issue_tile(it + 3, (it + 3) & 3); else CPCOMMIT();

        const float* As = smg + (it & 3) * GSTAGE;
        const float* Bs = As + BM * PA;
        #pragma unroll
        for (int kk = 0; kk < BKG; kk += 8) {
            uint32_t af[4][4];
            #pragma unroll
            for (int mf = 0; mf < 4; mf++) {
                int r = wm + mf * 16 + gid;
                af[mf][0] = __float_as_uint(As[(r    ) * PA + kk + tig]);
                af[mf][1] = __float_as_uint(As[(r + 8) * PA + kk + tig]);
                af[mf][2] = __float_as_uint(As[(r    ) * PA + kk + tig + 4]);
                af[mf][3] = __float_as_uint(As[(r + 8) * PA + kk + tig + 4]);
            }
            uint32_t bf[8][2];
            #pragma unroll
            for (int nt = 0; nt < 8; nt++) {
                int c = wn + nt * 8 + gid;
                bf[nt][0] = __float_as_uint(Bs[(kk + tig    ) * PB + c]);
                bf[nt][1] = __float_as_uint(Bs[(kk + tig + 4) * PB + c]);
            }
            #pragma unroll
            for (int mf = 0; mf < 4; mf++)
                #pragma unroll
                for (int nt = 0; nt < 8; nt++)
                    mma_tf32(acc[mf][nt], af[mf], bf[nt]);
        }
    }

    const float* bias = g.bias;
    float* C = g.C;
    #pragma unroll
    for (int mf = 0; mf < 4; mf++) {
        int r0 = m0 + wm + mf * 16 + gid;
        #pragma unroll
        for (int nt = 0; nt < 8; nt++) {
            int col = n0 + wn + nt * 8 + tig * 2;
            float b0 = bias ? bias[col] : 0.f;
            float b1 = bias ? bias[col + 1] : 0.f;
            if (r0 < M)
                *(float2*)&C[(size_t)r0 * DM + col] =
                    make_float2(acc[mf][nt].x + b0, acc[mf][nt].y + b1);
            if (r0 + 8 < M)
                *(float2*)&C[(size_t)(r0 + 8) * DM + col] =
                    make_float2(acc[mf][nt].z + b0, acc[mf][nt].w + b1);
        }
    }
}

// ------------- RMSNorm + RoPE -> tf32-rounded [H, S_TOT, HD] --------------------
// q is additionally pre-scaled by SM_SCALE.
__global__ __launch_bounds__(128) void qkv_transform(
    const float* __restrict__ nqw, const float* __restrict__ nkw,
    const float* __restrict__ naqw, const float* __restrict__ nakw,
    const float* __restrict__ fcos, const float* __restrict__ fsin)
{
    const int s = blockIdx.x, h = blockIdx.y, d = threadIdx.x;
    const int lane = d & 31, wid = d >> 5;
    __shared__ float ws[4];
    const bool txt = s < S_TXT;
    const size_t roff = txt ? (size_t)s * DM : (size_t)(s - S_TXT) * DM;
    const size_t col = roff + h * HD + d;
    const float* xq = txt ? g_pq_txt : g_pq_img;
    const float* xk = txt ? g_pk_txt : g_pk_img;
    const float* xv = txt ? g_pv_txt : g_pv_img;
    const float wq = txt ? naqw[d] : nqw[d];
    const float wk = txt ? nakw[d] : nkw[d];
    const float c = fcos[s * HD + d];
    const float sn = fsin[s * HD + d];
    const size_t oidx = ((size_t)h * S_TOT + s) * HD + d;

    float q = xq[col];
    float t2 = q * q;
    #pragma unroll
    for (int off = 16; off; off >>= 1) t2 += __shfl_xor_sync(0xffffffffu, t2, off);
    if (lane == 0) ws[wid] = t2;
    __syncthreads();
    float tot = ws[0] + ws[1] + ws[2] + ws[3];
    float qn = q * rsqrtf(tot * (1.f / HD) + 1e-6f) * wq;
    float pq = __shfl_xor_sync(0xffffffffu, qn, 1);
    float rotq = (d & 1) ? pq : -pq;
    g_q[oidx] = tf32r((qn * c + rotq * sn) * SM_SCALE);
    __syncthreads();

    float k = xk[col];
    t2 = k * k;
    #pragma unroll
    for (int off = 16; off; off >>= 1) t2 += __shfl_xor_sync(0xffffffffu, t2, off);
    if (lane == 0) ws[wid] = t2;
    __syncthreads();
    tot = ws[0] + ws[1] + ws[2] + ws[3];
    float kn = k * rsqrtf(tot * (1.f / HD) + 1e-6f) * wk;
    float pk = __shfl_xor_sync(0xffffffffu, kn, 1);
    float rotk = (d & 1) ? pk : -pk;
    g_k[oidx] = tf32r(kn * c + rotk * sn);

    g_v[oidx] = tf32r(xv[col]);
}

// ---------------- tensor-core flash attention, cp.async double-buffered ---------
#define AQ 128
#define AKV 64
#define QPAD 132
#define VPAD 136
#define OFF_K(st) (AQ * QPAD + (st) * (AKV * QPAD))
#define OFF_V(st) (AQ * QPAD + 2 * (AKV * QPAD) + (st) * (AKV * VPAD))
#define ATTN_SMEM ((AQ * QPAD + 2 * AKV * QPAD + 2 * AKV * VPAD) * 4)

__global__ __launch_bounds__(256) void attn_mma()
{
    extern __shared__ float sm[];
    const int qt = blockIdx.x, h = blockIdx.y;
    const int tid = threadIdx.x;
    const int warp = tid >> 5, lane = tid & 31;
    const int gid = lane >> 2, tig = lane & 3;
    const int wm = warp * 16;

    const float* Qg = g_q + ((size_t)h * S_TOT + qt * AQ) * HD;
    const float* Kg = g_k + (size_t)h * S_TOT * HD;
    const float* Vg = g_v + (size_t)h * S_TOT * HD;

    auto issue_kv = [&](int kt, int st) {
        float* Ks = sm + OFF_K(st);
        float* Vs = sm + OFF_V(st);
        const float* Kt = Kg + (size_t)kt * AKV * HD;
        const float* Vt = Vg + (size_t)kt * AKV * HD;
        #pragma unroll
        for (int i = 0; i < 8; i++) {
            int c = tid + i * 256;               // 2048 chunks
            int r = c >> 5, col = (c & 31) * 4;
            uint32_t dk = (uint32_t)__cvta_generic_to_shared(&Ks[r * QPAD + col]);
            CPA16(dk, &Kt[(size_t)r * HD + col], 16);
            uint32_t dv = (uint32_t)__cvta_generic_to_shared(&Vs[r * VPAD + col]);
            CPA16(dv, &Vt[(size_t)r * HD + col], 16);
        }
    };

    // prologue: Q + KV tile 0 in one group
    {
        #pragma unroll
        for (int i = 0; i < 16; i++) {
            int c = tid + i * 256;               // 4096 chunks
            int r = c >> 5, col = (c & 31) * 4;
            uint32_t dq = (uint32_t)__cvta_generic_to_shared(&sm[r * QPAD + col]);
            CPA16(dq, &Qg[(size_t)r * HD + col], 16);
        }
        issue_kv(0, 0);
        CPCOMMIT();
    }

    float m0 = -1e30f, m1 = -1e30f, l0 = 0.f, l1 = 0.f;
    float4 o[16];
    #pragma unroll
    for (int i = 0; i < 16; i++) o[i] = make_float4(0.f, 0.f, 0.f, 0.f);

    const float* Qs = sm;
    for (int kt = 0; kt < S_TOT / AKV; kt++) {
        const int st = kt & 1;
        CPWAIT(0);
        __syncthreads();
        if (kt + 1 < S_TOT / AKV) { issue_kv(kt + 1, st ^ 1); CPCOMMIT(); }

        const float* Ks = sm + OFF_K(st);
        const float* Vs = sm + OFF_V(st);

        // S = Qs @ Ks^T : 16 x 64 per warp
        float4 s[8];
        #pragma unroll
        for (int nb = 0; nb < 8; nb++) s[nb] = make_float4(0.f, 0.f, 0.f, 0.f);
        #pragma unroll
        for (int ks = 0; ks < HD / 8; ks++) {
            const int kk = ks * 8;
            uint32_t a[4];
            a[0] = __float_as_uint(Qs[(wm + gid    ) * QPAD + kk + tig]);
            a[1] = __float_as_uint(Qs[(wm + gid + 8) * QPAD + kk + tig]);
            a[2] = __float_as_uint(Qs[(wm + gid    ) * QPAD + kk + tig + 4]);
            a[3] = __float_as_uint(Qs[(wm + gid + 8) * QPAD + kk + tig + 4]);
            #pragma unroll
            for (int nb = 0; nb < 8; nb++) {
                uint32_t b[2];
                b[0] = __float_as_uint(Ks[(nb * 8 + gid) * QPAD + kk + tig]);
                b[1] = __float_as_uint(Ks[(nb * 8 + gid) * QPAD + kk + tig + 4]);
                mma_tf32(s[nb], a, b);
            }
        }

        // online softmax
        float mx0 = m0, mx1 = m1;
        #pragma unroll
        for (int nb = 0; nb < 8; nb++) {
            mx0 = fmaxf(mx0, fmaxf(s[nb].x, s[nb].y));
            mx1 = fmaxf(mx1, fmaxf(s[nb].z, s[nb].w));
        }
        mx0 = fmaxf(mx0, __shfl_xor_sync(0xffffffffu, mx0, 1));
        mx0 = fmaxf(mx0, __shfl_xor_sync(0xffffffffu, mx0, 2));
        mx1 = fmaxf(mx1, __shfl_xor_sync(0xffffffffu, mx1, 1));
        mx1 = fmaxf(mx1, __shfl_xor_sync(0xffffffffu, mx1, 2));
        const float c0 = __expf(m0 - mx0);
        const float c1 = __expf(m1 - mx1);
        m0 = mx0; m1 = mx1;
        float ls0 = 0.f, ls1 = 0.f;
        #pragma unroll
        for (int nb = 0; nb < 8; nb++) {
            s[nb].x = __expf(s[nb].x - m0);
            s[nb].y = __expf(s[nb].y - m0);
            s[nb].z = __expf(s[nb].z - m1);
            s[nb].w = __expf(s[nb].w - m1);
            ls0 += s[nb].x + s[nb].y;
            ls1 += s[nb].z + s[nb].w;
        }
        l0 = l0 * c0 + ls0;
        l1 = l1 * c1 + ls1;
        #pragma unroll
        for (int i = 0; i < 16; i++) {
            o[i].x *= c0; o[i].y *= c0; o[i].z *= c1; o[i].w *= c1;
        }

        // O += P @ V (P A-frags via quad shuffles; P needs rna conversion)
        const int srcA = (lane & ~3) | (tig >> 1);
        const int srcB = srcA + 2;
        #pragma unroll
        for (int kb = 0; kb < 8; kb++) {
            float xA = __shfl_sync(0xffffffffu, s[kb].x, srcA);
            float yA = __shfl_sync(0xffffffffu, s[kb].y, srcA);
            float zA = __shfl_sync(0xffffffffu, s[kb].z, srcA);
            float wA = __shfl_sync(0xffffffffu, s[kb].w, srcA);
            float xB = __shfl_sync(0xffffffffu, s[kb].x, srcB);
            float yB = __shfl_sync(0xffffffffu, s[kb].y, srcB);
            float zB = __shfl_sync(0xffffffffu, s[kb].z, srcB);
            float wB = __shfl_sync(0xffffffffu, s[kb].w, srcB);
            uint32_t a[4];
            a[0] = f2tf32((tig & 1) ? yA : xA);
            a[1] = f2tf32((tig & 1) ? wA : zA);
            a[2] = f2tf32((tig & 1) ? yB : xB);
            a[3] = f2tf32((tig & 1) ? wB : zB);
            #pragma unroll
            for (int nb = 0; nb < 16; nb++) {
                uint32_t b[2];
                b[0] = __float_as_uint(Vs[(kb * 8 + tig    ) * VPAD + nb * 8 + gid]);
                b[1] = __float_as_uint(Vs[(kb * 8 + tig + 4) * VPAD + nb * 8 + gid]);
                mma_tf32(o[nb], a, b);
            }
        }
    }

    l0 += __shfl_xor_sync(0xffffffffu, l0, 1);
    l0 += __shfl_xor_sync(0xffffffffu, l0, 2);
    l1 += __shfl_xor_sync(0xffffffffu, l1, 1);
    l1 += __shfl_xor_sync(0xffffffffu, l1, 2);
    const float i0 = 1.f / l0, i1 = 1.f / l1;

    const int r0 = qt * AQ + wm + gid;
    float* O0 = g_o + ((size_t)h * S_TOT + r0) * HD;
    float* O1 = O0 + 8 * HD;
    #pragma unroll
    for (int nb = 0; nb < 16; nb++) {
        int col = nb * 8 + tig * 2;
        *(float2*)&O0[col] = make_float2(o[nb].x * i0, o[nb].y * i0);
        *(float2*)&O1[col] = make_float2(o[nb].z * i1, o[nb].w * i1);
    }
}

// ------- adapter 4-key cross-attention + merge (tf32-rounded hs) ----------------
// g_q is pre-scaled by SM_SCALE, so scores need no extra scale.
// Single-sync version: 4 parallel warp reductions + one smem exchange.
__global__ __launch_bounds__(128) void merge_adapter(const float* __restrict__ bscale)
{
    const int s = blockIdx.x, h = blockIdx.y, d = threadIdx.x;
    const int lane = d & 31, wid = d >> 5;
    __shared__ float sred[4][4];
    const size_t qidx = ((size_t)h * S_TOT + s) * HD + d;
    const float qv = g_q[qidx];
    const int hcol = h * HD + d;

    float p0 = qv * g_ka[0 * DM + hcol];
    float p1 = qv * g_ka[1 * DM + hcol];
    float p2 = qv * g_ka[2 * DM + hcol];
    float p3 = qv * g_ka[3 * DM + hcol];
    #pragma unroll
    for (int off = 16; off; off >>= 1) {
        p0 += __shfl_xor_sync(0xffffffffu, p0, off);
        p1 += __shfl_xor_sync(0xffffffffu, p1, off);
        p2 += __shfl_xor_sync(0xffffffffu, p2, off);
        p3 += __shfl_xor_sync(0xffffffffu, p3, off);
    }
    if (lane == 0) {
        sred[wid][0] = p0; sred[wid][1] = p1;
        sred[wid][2] = p2; sred[wid][3] = p3;
    }
    __syncthreads();
    float d0 = sred[0][0] + sred[1][0] + sred[2][0] + sred[3][0];
    float d1 = sred[0][1] + sred[1][1] + sred[2][1] + sred[3][1];
    float d2 = sred[0][2] + sred[1][2] + sred[2][2] + sred[3][2];
    float d3 = sred[0][3] + sred[1][3] + sred[2][3] + sred[3][3];

    float mx = fmaxf(fmaxf(d0, d1), fmaxf(d2, d3));
    float e0 = __expf(d0 - mx), e1 = __expf(d1 - mx);
    float e2 = __expf(d2 - mx), e3 = __expf(d3 - mx);
    float inv = 1.f / (e0 + e1 + e2 + e3);
    float vd = (e0 * g_va[0 * DM + hcol] + e1 * g_va[1 * DM + hcol] +
                e2 * g_va[2 * DM + hcol] + e3 * g_va[3 * DM + hcol]) * inv;
    g_hs[(size_t)s * DM + hcol] = tf32r(g_o[qidx] + bscale[0] * vd);
}

// -------------------------------- launch ---------------------------------------
extern "C" void kernel_launch(void* const* d_in, const int* in_sizes, int n_in,
                              void* d_out, int out_size)
{
    const float* hidden = (const float*)d_in[0];
    const float* enc    = (const float*)d_in[1];
    const float* adapt  = (const float*)d_in[2];
    const float* fcos   = (const float*)d_in[3];
    const float* fsin   = (const float*)d_in[4];
    const float* Wq  = (const float*)d_in[5];  const float* bq  = (const float*)d_in[6];
    const float* Wk  = (const float*)d_in[7];  const float* bk  = (const float*)d_in[8];
    const float* Wv  = (const float*)d_in[9];  const float* bv  = (const float*)d_in[10];
    const float* nqw = (const float*)d_in[11]; const float* nkw = (const float*)d_in[12];
    const float* Wqa = (const float*)d_in[13]; const float* bqa = (const float*)d_in[14];
    const float* Wka = (const float*)d_in[15]; const float* bka = (const float*)d_in[16];
    const float* Wva = (const float*)d_in[17]; const float* bva = (const float*)d_in[18];
    const float* naqw = (const float*)d_in[19]; const float* nakw = (const float*)d_in[20];
    const float* Wo  = (const float*)d_in[21]; const float* bo  = (const float*)d_in[22];
    const float* Woa = (const float*)d_in[23]; const float* boa = (const float*)d_in[24];
    const float* Wkad = (const float*)d_in[25]; const float* Wvad = (const float*)d_in[26];
    const float* bscale = (const float*)d_in[27];
    float* out = (float*)d_out;

    float *pq_img, *pk_img, *pv_img, *pq_txt, *pk_txt, *pv_txt, *ka, *va, *hs;
    float *chid, *cenc, *cad, *cWq, *cWk, *cWv, *cWqa, *cWka, *cWva, *cWo, *cWoa,
          *cWkad, *cWvad;
    cudaGetSymbolAddress((void**)&pq_img, g_pq_img);
    cudaGetSymbolAddress((void**)&pk_img, g_pk_img);
    cudaGetSymbolAddress((void**)&pv_img, g_pv_img);
    cudaGetSymbolAddress((void**)&pq_txt, g_pq_txt);
    cudaGetSymbolAddress((void**)&pk_txt, g_pk_txt);
    cudaGetSymbolAddress((void**)&pv_txt, g_pv_txt);
    cudaGetSymbolAddress((void**)&ka, g_ka);
    cudaGetSymbolAddress((void**)&va, g_va);
    cudaGetSymbolAddress((void**)&hs, g_hs);
    cudaGetSymbolAddress((void**)&chid, g_chid);
    cudaGetSymbolAddress((void**)&cenc, g_cenc);
    cudaGetSymbolAddress((void**)&cad, g_cad);
    cudaGetSymbolAddress((void**)&cWq, g_cWq);
    cudaGetSymbolAddress((void**)&cWk, g_cWk);
    cudaGetSymbolAddress((void**)&cWv, g_cWv);
    cudaGetSymbolAddress((void**)&cWqa, g_cWqa);
    cudaGetSymbolAddress((void**)&cWka, g_cWka);
    cudaGetSymbolAddress((void**)&cWva, g_cWva);
    cudaGetSymbolAddress((void**)&cWo, g_cWo);
    cudaGetSymbolAddress((void**)&cWoa, g_cWoa);
    cudaGetSymbolAddress((void**)&cWkad, g_cWkad);
    cudaGetSymbolAddress((void**)&cWvad, g_cWvad);

    cudaFuncSetAttribute(attn_mma, cudaFuncAttributeMaxDynamicSharedMemorySize,
                         ATTN_SMEM);
    cudaFuncSetAttribute(gemm_ca, cudaFuncAttributeMaxDynamicSharedMemorySize,
                         GSMEM);

    // --- pre-round everything the GEMMs consume ---
    CV13 cv;
    cv.e[0]  = { hidden, chid,  S_IMG * DM };
    cv.e[1]  = { enc,    cenc,  S_TXT * DM };
    cv.e[2]  = { adapt,  cad,   ATOK * ADIM };
    cv.e[3]  = { Wq,     cWq,   DM * DM };
    cv.e[4]  = { Wk,     cWk,   DM * DM };
    cv.e[5]  = { Wv,     cWv,   DM * DM };
    cv.e[6]  = { Wqa,    cWqa,  DM * DM };
    cv.e[7]  = { Wka,    cWka,  DM * DM };
    cv.e[8]  = { Wva,    cWva,  DM * DM };
    cv.e[9]  = { Wo,     cWo,   DM * DM };
    cv.e[10] = { Woa,    cWoa,  DM * DM };
    cv.e[11] = { Wkad,   cWkad, ADIM * DM };
    cv.e[12] = { Wvad,   cWvad, ADIM * DM };
    prep_cvt<<<dim3((DM * DM + 1023) / 1024, 13), 256>>>(cv);

    // --- all 6 QKV projections in one launch ---
    GB6 qkv;
    qkv.e[0] = { chid, cWq,  bq,  pq_img, S_IMG, DM };
    qkv.e[1] = { chid, cWk,  bk,  pk_img, S_IMG, DM };
    qkv.e[2] = { chid, cWv,  bv,  pv_img, S_IMG, DM };
    qkv.e[3] = { cenc, cWqa, bqa, pq_txt, S_TXT, DM };
    qkv.e[4] = { cenc, cWka, bka, pk_txt, S_TXT, DM };
    qkv.e[5] = { cenc, cWva, bva, pv_txt, S_TXT, DM };
    gemm_ca<<<dim3(DM / BN, S_IMG / BM, 6), 256, GSMEM>>>(qkv);

    // --- adapter K/V (M=4, K=1024) ---
    GB6 ad;
    ad.e[0] = { cad, cWkad, (const float*)0, ka, ATOK, ADIM };
    ad.e[1] = { cad, cWvad, (const float*)0, va, ATOK, ADIM };
    ad.e[2] = ad.e[0]; ad.e[3] = ad.e[0]; ad.e[4] = ad.e[0]; ad.e[5] = ad.e[0];
    gemm_ca<<<dim3(DM / BN, 1, 2), 256, GSMEM>>>(ad);

    // RMSNorm + RoPE + head layout (tf32-rounded, q pre-scaled)
    qkv_transform<<<dim3(S_TOT, NH), 128>>>(nqw, nkw, naqw, nakw, fcos, fsin);
    // joint flash attention (tf32 tensor cores, cp.async double buffer)
    attn_mma<<<dim3(S_TOT / AQ, NH), 256, ATTN_SMEM>>>();
    // adapter attention + merge (writes tf32-rounded hs)
    merge_adapter<<<dim3(S_TOT, NH), 128>>>(bscale);

    // --- both output projections in one launch ---
    GB6 op;
    op.e[0] = { hs + (size_t)S_TXT * DM, cWo,  bo,  out,                      S_IMG, DM };
    op.e[1] = { hs,                      cWoa, boa, out + (size_t)S_IMG * DM, S_TXT, DM };
    op.e[2] = op.e[0]; op.e[3] = op.e[0]; op.e[4] = op.e[0]; op.e[5] = op.e[0];
    gemm_ca<<<dim3(DM / BN, S_IMG / BM, 2), 256, GSMEM>>>(op);
}

// round 10
// speedup vs baseline: 1.0589x; 1.0589x over previous
#include <cuda_runtime.h>
#include <math.h>
#include <stdint.h>

#define S_IMG 2048
#define S_TXT 512
#define S_TOT 2560
#define DM    3072
#define NH    24
#define HD    128
#define ATOK  4
#define ADIM  1024
#define SM_SCALE 0.08838834764831845f  /* 1/sqrt(128) */

// ---------------- scratch (device globals; no allocation allowed) ----------------
__device__ float g_pq_img[(size_t)S_IMG * DM];
__device__ float g_pk_img[(size_t)S_IMG * DM];
__device__ float g_pv_img[(size_t)S_IMG * DM];
__device__ float g_pq_txt[(size_t)S_TXT * DM];
__device__ float g_pk_txt[(size_t)S_TXT * DM];
__device__ float g_pv_txt[(size_t)S_TXT * DM];
__device__ float g_q[(size_t)NH * S_TOT * HD];
__device__ float g_k[(size_t)NH * S_TOT * HD];
__device__ float g_v[(size_t)NH * S_TOT * HD];
__device__ float g_hs[(size_t)S_TOT * DM];
__device__ float g_ka[ATOK * DM];
__device__ float g_va[ATOK * DM];
// tf32-pre-rounded copies (exact-truncation path for mma)
__device__ float g_chid[(size_t)S_IMG * DM];
__device__ float g_cenc[(size_t)S_TXT * DM];
__device__ float g_cad[ATOK * ADIM];
__device__ float g_cWq[(size_t)DM * DM];
__device__ float g_cWk[(size_t)DM * DM];
__device__ float g_cWv[(size_t)DM * DM];
__device__ float g_cWqa[(size_t)DM * DM];
__device__ float g_cWka[(size_t)DM * DM];
__device__ float g_cWva[(size_t)DM * DM];
__device__ float g_cWo[(size_t)DM * DM];
__device__ float g_cWoa[(size_t)DM * DM];
__device__ float g_cWkad[(size_t)ADIM * DM];
__device__ float g_cWvad[(size_t)ADIM * DM];

// ------------------------- helpers ----------------------------------------------
__device__ __forceinline__ uint32_t f2tf32(float f) {
    uint32_t r;
    asm("cvt.rna.tf32.f32 %0, %1;" : "=r"(r) : "f"(f));
    return r;
}
__device__ __forceinline__ float tf32r(float f) { return __uint_as_float(f2tf32(f)); }
__device__ __forceinline__ float4 cvt4(float4 v) {
    return make_float4(tf32r(v.x), tf32r(v.y), tf32r(v.z), tf32r(v.w));
}
__device__ __forceinline__ void mma_tf32(float4& d, const uint32_t a[4],
                                         const uint32_t b[2]) {
    asm volatile(
        "mma.sync.aligned.m16n8k8.row.col.f32.tf32.tf32.f32 "
        "{%0,%1,%2,%3}, {%4,%5,%6,%7}, {%8,%9}, {%0,%1,%2,%3};\n"
        : "+f"(d.x), "+f"(d.y), "+f"(d.z), "+f"(d.w)
        : "r"(a[0]), "r"(a[1]), "r"(a[2]), "r"(a[3]), "r"(b[0]), "r"(b[1]));
}
#define CPA16(dst, src, pb) \
    asm volatile("cp.async.cg.shared.global [%0], [%1], 16, %2;\n" \
                 :: "r"(dst), "l"(src), "r"(pb))
#define CPCOMMIT() asm volatile("cp.async.commit_group;\n" ::)
#define CPWAIT(n)  asm volatile("cp.async.wait_group %0;\n" :: "n"(n))

// ------------------------- pre-round pass ----------------------------------------
struct CV { const float* s; float* d; int n; };
struct CV13 { CV e[13]; };
__global__ __launch_bounds__(256) void prep_cvt(CV13 t)
{
    const CV c = t.e[blockIdx.y];
    int idx = (blockIdx.x * 256 + threadIdx.x) * 4;
    if (idx < c.n)
        *(float4*)&c.d[idx] = cvt4(*(const float4*)&c.s[idx]);
}

// --------- batched cp.async tf32 GEMM: C = A[M,K] @ W[K,3072] + bias -------------
// 3-stage pipeline, CTA tile 128x128, BK=32. A/W must be pre-rounded to tf32.
// (R7 proven configuration.)
#define BM 128
#define BN 128
#define BKG 32
#define PA 36     /* frag bank = 4*gid + tig (+4k per kk), bijective */
#define PB 136    /* frag bank = 8*tig + gid, bijective */
#define GSTAGE (BM * PA + BKG * PB)        /* floats per stage = 8960 */
#define GSMEM  (3 * GSTAGE * 4)            /* 107520 B */

struct GB { const float* A; const float* W; const float* bias; float* C; int M; int K; };
struct GB6 { GB e[6]; };

__global__ __launch_bounds__(256, 2) void gemm_ca(GB6 ga)
{
    const GB g = ga.e[blockIdx.z];
    const int M = g.M, K = g.K;
    const int m0 = blockIdx.y * BM;
    if (m0 >= M) return;
    const int n0 = blockIdx.x * BN;

    extern __shared__ float smg[];
    const float* __restrict__ A = g.A;
    const float* __restrict__ W = g.W;
    const int tid  = threadIdx.x;
    const int warp = tid >> 5, lane = tid & 31;
    const int gid  = lane >> 2, tig = lane & 3;
    const int wm = (warp & 3) * 32;
    const int wn = (warp >> 2) * 64;

    const int nIters = K / BKG;

    auto issue_tile = [&](int it, int stage) {
        float* As = smg + stage * GSTAGE;
        float* Bs = As + BM * PA;
        const int k0 = it * BKG;
        #pragma unroll
        for (int i = 0; i < 4; i++) {
            int c = tid + i * 256;
            int r = c >> 3, col = (c & 7) * 4;
            uint32_t dst = (uint32_t)__cvta_generic_to_shared(&As[r * PA + col]);
            const float* src = &A[(size_t)(m0 + r) * K + k0 + col];
            CPA16(dst, src, (m0 + r < M) ? 16 : 0);
        }
        #pragma unroll
        for (int i = 0; i < 4; i++) {
            int c = tid + i * 256;
            int r = c >> 5, col = (c & 31) * 4;
            uint32_t dst = (uint32_t)__cvta_generic_to_shared(&Bs[r * PB + col]);
            const float* src = &W[(size_t)(k0 + r) * DM + n0 + col];
            CPA16(dst, src, 16);
        }
        CPCOMMIT();
    };

    float4 acc[2][8];
    #pragma unroll
    for (int i = 0; i < 2; i++)
        #pragma unroll
        for (int j = 0; j < 8; j++) acc[i][j] = make_float4(0.f, 0.f, 0.f, 0.f);

    issue_tile(0, 0);
    if (nIters > 1) issue_tile(1, 1);

    for (int it = 0; it < nIters; it++) {
        if (it + 1 < nIters) { CPWAIT(1); } else { CPWAIT(0); }
        __syncthreads();
        if (it + 2 < nIters) issue_tile(it + 2, (it + 2) % 3);

        const float* As = smg + (it % 3) * GSTAGE;
        const float* Bs = As + BM * PA;
        #pragma unroll
        for (int kk = 0; kk < BKG; kk += 8) {
            uint32_t af[2][4];
            #pragma unroll
            for (int mt = 0; mt < 2; mt++) {
                int r = wm + mt * 16 + gid;
                af[mt][0] = __float_as_uint(As[(r    ) * PA + kk + tig]);
                af[mt][1] = __float_as_uint(As[(r + 8) * PA + kk + tig]);
                af[mt][2] = __float_as_uint(As[(r    ) * PA + kk + tig + 4]);
                af[mt][3] = __float_as_uint(As[(r + 8) * PA + kk + tig + 4]);
            }
            uint32_t bf[8][2];
            #pragma unroll
            for (int nt = 0; nt < 8; nt++) {
                int c = wn + nt * 8 + gid;
                bf[nt][0] = __float_as_uint(Bs[(kk + tig    ) * PB + c]);
                bf[nt][1] = __float_as_uint(Bs[(kk + tig + 4) * PB + c]);
            }
            #pragma unroll
            for (int mt = 0; mt < 2; mt++)
                #pragma unroll
                for (int nt = 0; nt < 8; nt++)
                    mma_tf32(acc[mt][nt], af[mt], bf[nt]);
        }
        __syncthreads();
    }

    const float* bias = g.bias;
    float* C = g.C;
    #pragma unroll
    for (int mt = 0; mt < 2; mt++) {
        int r0 = m0 + wm + mt * 16 + gid;
        #pragma unroll
        for (int nt = 0; nt < 8; nt++) {
            int col = n0 + wn + nt * 8 + tig * 2;
            float b0 = bias ? bias[col] : 0.f;
            float b1 = bias ? bias[col + 1] : 0.f;
            if (r0 < M)
                *(float2*)&C[(size_t)r0 * DM + col] =
                    make_float2(acc[mt][nt].x + b0, acc[mt][nt].y + b1);
            if (r0 + 8 < M)
                *(float2*)&C[(size_t)(r0 + 8) * DM + col] =
                    make_float2(acc[mt][nt].z + b0, acc[mt][nt].w + b1);
        }
    }
}

// ------------- RMSNorm + RoPE -> tf32-rounded [H, S_TOT, HD] --------------------
// q is additionally pre-scaled by SM_SCALE.
__global__ __launch_bounds__(128) void qkv_transform(
    const float* __restrict__ nqw, const float* __restrict__ nkw,
    const float* __restrict__ naqw, const float* __restrict__ nakw,
    const float* __restrict__ fcos, const float* __restrict__ fsin)
{
    const int s = blockIdx.x, h = blockIdx.y, d = threadIdx.x;
    const int lane = d & 31, wid = d >> 5;
    __shared__ float ws[4];
    const bool txt = s < S_TXT;
    const size_t roff = txt ? (size_t)s * DM : (size_t)(s - S_TXT) * DM;
    const size_t col = roff + h * HD + d;
    const float* xq = txt ? g_pq_txt : g_pq_img;
    const float* xk = txt ? g_pk_txt : g_pk_img;
    const float* xv = txt ? g_pv_txt : g_pv_img;
    const float wq = txt ? naqw[d] : nqw[d];
    const float wk = txt ? nakw[d] : nkw[d];
    const float c = fcos[s * HD + d];
    const float sn = fsin[s * HD + d];
    const size_t oidx = ((size_t)h * S_TOT + s) * HD + d;

    float q = xq[col];
    float t2 = q * q;
    #pragma unroll
    for (int off = 16; off; off >>= 1) t2 += __shfl_xor_sync(0xffffffffu, t2, off);
    if (lane == 0) ws[wid] = t2;
    __syncthreads();
    float tot = ws[0] + ws[1] + ws[2] + ws[3];
    float qn = q * rsqrtf(tot * (1.f / HD) + 1e-6f) * wq;
    float pq = __shfl_xor_sync(0xffffffffu, qn, 1);
    float rotq = (d & 1) ? pq : -pq;
    g_q[oidx] = tf32r((qn * c + rotq * sn) * SM_SCALE);
    __syncthreads();

    float k = xk[col];
    t2 = k * k;
    #pragma unroll
    for (int off = 16; off; off >>= 1) t2 += __shfl_xor_sync(0xffffffffu, t2, off);
    if (lane == 0) ws[wid] = t2;
    __syncthreads();
    tot = ws[0] + ws[1] + ws[2] + ws[3];
    float kn = k * rsqrtf(tot * (1.f / HD) + 1e-6f) * wk;
    float pk = __shfl_xor_sync(0xffffffffu, kn, 1);
    float rotk = (d & 1) ? pk : -pk;
    g_k[oidx] = tf32r(kn * c + rotk * sn);

    g_v[oidx] = tf32r(xv[col]);
}

// ---------------- tensor-core flash attention, cp.async double-buffered ---------
// Fused epilogue: adapter 4-key cross-attention + merge -> writes g_hs directly.
#define AQ 128
#define AKV 64
#define QPAD 132
#define VPAD 136
#define OFF_K(st) (AQ * QPAD + (st) * (AKV * QPAD))
#define OFF_V(st) (AQ * QPAD + 2 * (AKV * QPAD) + (st) * (AKV * VPAD))
#define ATTN_SMEM ((AQ * QPAD + 2 * AKV * QPAD + 2 * AKV * VPAD) * 4)

__global__ __launch_bounds__(256) void attn_mma(const float* __restrict__ bscale)
{
    extern __shared__ float sm[];
    const int qt = blockIdx.x, h = blockIdx.y;
    const int tid = threadIdx.x;
    const int warp = tid >> 5, lane = tid & 31;
    const int gid = lane >> 2, tig = lane & 3;
    const int wm = warp * 16;

    const float* Qg = g_q + ((size_t)h * S_TOT + qt * AQ) * HD;
    const float* Kg = g_k + (size_t)h * S_TOT * HD;
    const float* Vg = g_v + (size_t)h * S_TOT * HD;

    auto issue_kv = [&](int kt, int st) {
        float* Ks = sm + OFF_K(st);
        float* Vs = sm + OFF_V(st);
        const float* Kt = Kg + (size_t)kt * AKV * HD;
        const float* Vt = Vg + (size_t)kt * AKV * HD;
        #pragma unroll
        for (int i = 0; i < 8; i++) {
            int c = tid + i * 256;               // 2048 chunks
            int r = c >> 5, col = (c & 31) * 4;
            uint32_t dk = (uint32_t)__cvta_generic_to_shared(&Ks[r * QPAD + col]);
            CPA16(dk, &Kt[(size_t)r * HD + col], 16);
            uint32_t dv = (uint32_t)__cvta_generic_to_shared(&Vs[r * VPAD + col]);
            CPA16(dv, &Vt[(size_t)r * HD + col], 16);
        }
    };

    // prologue: Q + KV tile 0 in one group
    {
        #pragma unroll
        for (int i = 0; i < 16; i++) {
            int c = tid + i * 256;               // 4096 chunks
            int r = c >> 5, col = (c & 31) * 4;
            uint32_t dq = (uint32_t)__cvta_generic_to_shared(&sm[r * QPAD + col]);
            CPA16(dq, &Qg[(size_t)r * HD + col], 16);
        }
        issue_kv(0, 0);
        CPCOMMIT();
    }

    float m0 = -1e30f, m1 = -1e30f, l0 = 0.f, l1 = 0.f;
    float4 o[16];
    #pragma unroll
    for (int i = 0; i < 16; i++) o[i] = make_float4(0.f, 0.f, 0.f, 0.f);

    const float* Qs = sm;
    for (int kt = 0; kt < S_TOT / AKV; kt++) {
        const int st = kt & 1;
        CPWAIT(0);
        __syncthreads();
        if (kt + 1 < S_TOT / AKV) { issue_kv(kt + 1, st ^ 1); CPCOMMIT(); }

        const float* Ks = sm + OFF_K(st);
        const float* Vs = sm + OFF_V(st);

        // S = Qs @ Ks^T : 16 x 64 per warp
        float4 s[8];
        #pragma unroll
        for (int nb = 0; nb < 8; nb++) s[nb] = make_float4(0.f, 0.f, 0.f, 0.f);
        #pragma unroll
        for (int ks = 0; ks < HD / 8; ks++) {
            const int kk = ks * 8;
            uint32_t a[4];
            a[0] = __float_as_uint(Qs[(wm + gid    ) * QPAD + kk + tig]);
            a[1] = __float_as_uint(Qs[(wm + gid + 8) * QPAD + kk + tig]);
            a[2] = __float_as_uint(Qs[(wm + gid    ) * QPAD + kk + tig + 4]);
            a[3] = __float_as_uint(Qs[(wm + gid + 8) * QPAD + kk + tig + 4]);
            #pragma unroll
            for (int nb = 0; nb < 8; nb++) {
                uint32_t b[2];
                b[0] = __float_as_uint(Ks[(nb * 8 + gid) * QPAD + kk + tig]);
                b[1] = __float_as_uint(Ks[(nb * 8 + gid) * QPAD + kk + tig + 4]);
                mma_tf32(s[nb], a, b);
            }
        }

        // online softmax
        float mx0 = m0, mx1 = m1;
        #pragma unroll
        for (int nb = 0; nb < 8; nb++) {
            mx0 = fmaxf(mx0, fmaxf(s[nb].x, s[nb].y));
            mx1 = fmaxf(mx1, fmaxf(s[nb].z, s[nb].w));
        }
        mx0 = fmaxf(mx0, __shfl_xor_sync(0xffffffffu, mx0, 1));
        mx0 = fmaxf(mx0, __shfl_xor_sync(0xffffffffu, mx0, 2));
        mx1 = fmaxf(mx1, __shfl_xor_sync(0xffffffffu, mx1, 1));
        mx1 = fmaxf(mx1, __shfl_xor_sync(0xffffffffu, mx1, 2));
        const float c0 = __expf(m0 - mx0);
        const float c1 = __expf(m1 - mx1);
        m0 = mx0; m1 = mx1;
        float ls0 = 0.f, ls1 = 0.f;
        #pragma unroll
        for (int nb = 0; nb < 8; nb++) {
            s[nb].x = __expf(s[nb].x - m0);
            s[nb].y = __expf(s[nb].y - m0);
            s[nb].z = __expf(s[nb].z - m1);
            s[nb].w = __expf(s[nb].w - m1);
            ls0 += s[nb].x + s[nb].y;
            ls1 += s[nb].z + s[nb].w;
        }
        l0 = l0 * c0 + ls0;
        l1 = l1 * c1 + ls1;
        #pragma unroll
        for (int i = 0; i < 16; i++) {
            o[i].x *= c0; o[i].y *= c0; o[i].z *= c1; o[i].w *= c1;
        }

        // O += P @ V (P A-frags via quad shuffles; P needs rna conversion)
        const int srcA = (lane & ~3) | (tig >> 1);
        const int srcB = srcA + 2;
        #pragma unroll
        for (int kb = 0; kb < 8; kb++) {
            float xA = __shfl_sync(0xffffffffu, s[kb].x, srcA);
            float yA = __shfl_sync(0xffffffffu, s[kb].y, srcA);
            float zA = __shfl_sync(0xffffffffu, s[kb].z, srcA);
            float wA = __shfl_sync(0xffffffffu, s[kb].w, srcA);
            float xB = __shfl_sync(0xffffffffu, s[kb].x, srcB);
            float yB = __shfl_sync(0xffffffffu, s[kb].y, srcB);
            float zB = __shfl_sync(0xffffffffu, s[kb].z, srcB);
            float wB = __shfl_sync(0xffffffffu, s[kb].w, srcB);
            uint32_t a[4];
            a[0] = f2tf32((tig & 1) ? yA : xA);
            a[1] = f2tf32((tig & 1) ? wA : zA);
            a[2] = f2tf32((tig & 1) ? yB : xB);
            a[3] = f2tf32((tig & 1) ? wB : zB);
            #pragma unroll
            for (int nb = 0; nb < 16; nb++) {
                uint32_t b[2];
                b[0] = __float_as_uint(Vs[(kb * 8 + tig    ) * VPAD + nb * 8 + gid]);
                b[1] = __float_as_uint(Vs[(kb * 8 + tig + 4) * VPAD + nb * 8 + gid]);
                mma_tf32(o[nb], a, b);
            }
        }
    }

    l0 += __shfl_xor_sync(0xffffffffu, l0, 1);
    l0 += __shfl_xor_sync(0xffffffffu, l0, 2);
    l1 += __shfl_xor_sync(0xffffffffu, l1, 1);
    l1 += __shfl_xor_sync(0xffffffffu, l1, 2);
    const float i0 = 1.f / l0, i1 = 1.f / l1;

    // ---- fused adapter cross-attention (Qs still resident; pre-scaled q) ----
    const int lr0 = wm + gid, lr1 = lr0 + 8;
    float sc0[ATOK], sc1[ATOK];
    #pragma unroll
    for (int t = 0; t < ATOK; t++) {
        const float* kap = &g_ka[t * DM + h * HD];
        float a0 = 0.f, a1 = 0.f;
        #pragma unroll
        for (int nb = 0; nb < 16; nb++) {
            int cc = nb * 8 + tig * 2;
            float k0v = kap[cc], k1v = kap[cc + 1];
            a0 += Qs[lr0 * QPAD + cc] * k0v + Qs[lr0 * QPAD + cc + 1] * k1v;
            a1 += Qs[lr1 * QPAD + cc] * k0v + Qs[lr1 * QPAD + cc + 1] * k1v;
        }
        a0 += __shfl_xor_sync(0xffffffffu, a0, 1);
        a0 += __shfl_xor_sync(0xffffffffu, a0, 2);
        a1 += __shfl_xor_sync(0xffffffffu, a1, 1);
        a1 += __shfl_xor_sync(0xffffffffu, a1, 2);
        sc0[t] = a0; sc1[t] = a1;
    }
    float w0[ATOK], w1[ATOK];
    {
        float mxa = fmaxf(fmaxf(sc0[0], sc0[1]), fmaxf(sc0[2], sc0[3]));
        float e0 = __expf(sc0[0] - mxa), e1 = __expf(sc0[1] - mxa);
        float e2 = __expf(sc0[2] - mxa), e3 = __expf(sc0[3] - mxa);
        float inv = 1.f / (e0 + e1 + e2 + e3);
        w0[0] = e0 * inv; w0[1] = e1 * inv; w0[2] = e2 * inv; w0[3] = e3 * inv;
    }
    {
        float mxa = fmaxf(fmaxf(sc1[0], sc1[1]), fmaxf(sc1[2], sc1[3]));
        float e0 = __expf(sc1[0] - mxa), e1 = __expf(sc1[1] - mxa);
        float e2 = __expf(sc1[2] - mxa), e3 = __expf(sc1[3] - mxa);
        float inv = 1.f / (e0 + e1 + e2 + e3);
        w1[0] = e0 * inv; w1[1] = e1 * inv; w1[2] = e2 * inv; w1[3] = e3 * inv;
    }
    const float bsc = bscale[0];

    const int s0 = qt * AQ + lr0;
    float* H0 = g_hs + (size_t)s0 * DM + h * HD;
    float* H1 = H0 + 8 * DM;
    #pragma unroll
    for (int nb = 0; nb < 16; nb++) {
        int cc = nb * 8 + tig * 2;
        int hcol = h * HD + cc;
        float va0a = g_va[0 * DM + hcol], va0b = g_va[0 * DM + hcol + 1];
        float va1a = g_va[1 * DM + hcol], va1b = g_va[1 * DM + hcol + 1];
        float va2a = g_va[2 * DM + hcol], va2b = g_va[2 * DM + hcol + 1];
        float va3a = g_va[3 * DM + hcol], va3b = g_va[3 * DM + hcol + 1];
        float vd0a = w0[0] * va0a + w0[1] * va1a + w0[2] * va2a + w0[3] * va3a;
        float vd0b = w0[0] * va0b + w0[1] * va1b + w0[2] * va2b + w0[3] * va3b;
        float vd1a = w1[0] * va0a + w1[1] * va1a + w1[2] * va2a + w1[3] * va3a;
        float vd1b = w1[0] * va0b + w1[1] * va1b + w1[2] * va2b + w1[3] * va3b;
        *(float2*)&H0[cc] = make_float2(tf32r(o[nb].x * i0 + bsc * vd0a),
                                        tf32r(o[nb].y * i0 + bsc * vd0b));
        *(float2*)&H1[cc] = make_float2(tf32r(o[nb].z * i1 + bsc * vd1a),
                                        tf32r(o[nb].w * i1 + bsc * vd1b));
    }
}

// -------------------------------- launch ---------------------------------------
extern "C" void kernel_launch(void* const* d_in, const int* in_sizes, int n_in,
                              void* d_out, int out_size)
{
    const float* hidden = (const float*)d_in[0];
    const float* enc    = (const float*)d_in[1];
    const float* adapt  = (const float*)d_in[2];
    const float* fcos   = (const float*)d_in[3];
    const float* fsin   = (const float*)d_in[4];
    const float* Wq  = (const float*)d_in[5];  const float* bq  = (const float*)d_in[6];
    const float* Wk  = (const float*)d_in[7];  const float* bk  = (const float*)d_in[8];
    const float* Wv  = (const float*)d_in[9];  const float* bv  = (const float*)d_in[10];
    const float* nqw = (const float*)d_in[11]; const float* nkw = (const float*)d_in[12];
    const float* Wqa = (const float*)d_in[13]; const float* bqa = (const float*)d_in[14];
    const float* Wka = (const float*)d_in[15]; const float* bka = (const float*)d_in[16];
    const float* Wva = (const float*)d_in[17]; const float* bva = (const float*)d_in[18];
    const float* naqw = (const float*)d_in[19]; const float* nakw = (const float*)d_in[20];
    const float* Wo  = (const float*)d_in[21]; const float* bo  = (const float*)d_in[22];
    const float* Woa = (const float*)d_in[23]; const float* boa = (const float*)d_in[24];
    const float* Wkad = (const float*)d_in[25]; const float* Wvad = (const float*)d_in[26];
    const float* bscale = (const float*)d_in[27];
    float* out = (float*)d_out;

    float *pq_img, *pk_img, *pv_img, *pq_txt, *pk_txt, *pv_txt, *ka, *va, *hs;
    float *chid, *cenc, *cad, *cWq, *cWk, *cWv, *cWqa, *cWka, *cWva, *cWo, *cWoa,
          *cWkad, *cWvad;
    cudaGetSymbolAddress((void**)&pq_img, g_pq_img);
    cudaGetSymbolAddress((void**)&pk_img, g_pk_img);
    cudaGetSymbolAddress((void**)&pv_img, g_pv_img);
    cudaGetSymbolAddress((void**)&pq_txt, g_pq_txt);
    cudaGetSymbolAddress((void**)&pk_txt, g_pk_txt);
    cudaGetSymbolAddress((void**)&pv_txt, g_pv_txt);
    cudaGetSymbolAddress((void**)&ka, g_ka);
    cudaGetSymbolAddress((void**)&va, g_va);
    cudaGetSymbolAddress((void**)&hs, g_hs);
    cudaGetSymbolAddress((void**)&chid, g_chid);
    cudaGetSymbolAddress((void**)&cenc, g_cenc);
    cudaGetSymbolAddress((void**)&cad, g_cad);
    cudaGetSymbolAddress((void**)&cWq, g_cWq);
    cudaGetSymbolAddress((void**)&cWk, g_cWk);
    cudaGetSymbolAddress((void**)&cWv, g_cWv);
    cudaGetSymbolAddress((void**)&cWqa, g_cWqa);
    cudaGetSymbolAddress((void**)&cWka, g_cWka);
    cudaGetSymbolAddress((void**)&cWva, g_cWva);
    cudaGetSymbolAddress((void**)&cWo, g_cWo);
    cudaGetSymbolAddress((void**)&cWoa, g_cWoa);
    cudaGetSymbolAddress((void**)&cWkad, g_cWkad);
    cudaGetSymbolAddress((void**)&cWvad, g_cWvad);

    cudaFuncSetAttribute(attn_mma, cudaFuncAttributeMaxDynamicSharedMemorySize,
                         ATTN_SMEM);
    cudaFuncSetAttribute(gemm_ca, cudaFuncAttributeMaxDynamicSharedMemorySize,
                         GSMEM);

    // --- pre-round everything the GEMMs consume ---
    CV13 cv;
    cv.e[0]  = { hidden, chid,  S_IMG * DM };
    cv.e[1]  = { enc,    cenc,  S_TXT * DM };
    cv.e[2]  = { adapt,  cad,   ATOK * ADIM };
    cv.e[3]  = { Wq,     cWq,   DM * DM };
    cv.e[4]  = { Wk,     cWk,   DM * DM };
    cv.e[5]  = { Wv,     cWv,   DM * DM };
    cv.e[6]  = { Wqa,    cWqa,  DM * DM };
    cv.e[7]  = { Wka,    cWka,  DM * DM };
    cv.e[8]  = { Wva,    cWva,  DM * DM };
    cv.e[9]  = { Wo,     cWo,   DM * DM };
    cv.e[10] = { Woa,    cWoa,  DM * DM };
    cv.e[11] = { Wkad,   cWkad, ADIM * DM };
    cv.e[12] = { Wvad,   cWvad, ADIM * DM };
    prep_cvt<<<dim3((DM * DM + 1023) / 1024, 13), 256>>>(cv);

    // --- all 6 QKV projections in one launch ---
    GB6 qkv;
    qkv.e[0] = { chid, cWq,  bq,  pq_img, S_IMG, DM };
    qkv.e[1] = { chid, cWk,  bk,  pk_img, S_IMG, DM };
    qkv.e[2] = { chid, cWv,  bv,  pv_img, S_IMG, DM };
    qkv.e[3] = { cenc, cWqa, bqa, pq_txt, S_TXT, DM };
    qkv.e[4] = { cenc, cWka, bka, pk_txt, S_TXT, DM };
    qkv.e[5] = { cenc, cWva, bva, pv_txt, S_TXT, DM };
    gemm_ca<<<dim3(DM / BN, S_IMG / BM, 6), 256, GSMEM>>>(qkv);

    // --- adapter K/V (M=4, K=1024) ---
    GB6 ad;
    ad.e[0] = { cad, cWkad, (const float*)0, ka, ATOK, ADIM };
    ad.e[1] = { cad, cWvad, (const float*)0, va, ATOK, ADIM };
    ad.e[2] = ad.e[0]; ad.e[3] = ad.e[0]; ad.e[4] = ad.e[0]; ad.e[5] = ad.e[0];
    gemm_ca<<<dim3(DM / BN, 1, 2), 256, GSMEM>>>(ad);

    // RMSNorm + RoPE + head layout (tf32-rounded, q pre-scaled)
    qkv_transform<<<dim3(S_TOT, NH), 128>>>(nqw, nkw, naqw, nakw, fcos, fsin);
    // joint flash attention + fused adapter merge -> g_hs
    attn_mma<<<dim3(S_TOT / AQ, NH), 256, ATTN_SMEM>>>(bscale);

    // --- both output projections in one launch ---
    GB6 op;
    op.e[0] = { hs + (size_t)S_TXT * DM, cWo,  bo,  out,                      S_IMG, DM };
    op.e[1] = { hs,                      cWoa, boa, out + (size_t)S_IMG * DM, S_TXT, DM };
    op.e[2] = op.e[0]; op.e[3] = op.e[0]; op.e[4] = op.e[0]; op.e[5] = op.e[0];
    gemm_ca<<<dim3(DM / BN, S_IMG / BM, 2), 256, GSMEM>>>(op);
}

// round 12
// speedup vs baseline: 1.4595x; 1.3783x over previous
#include <cuda_runtime.h>
#include <cuda_fp16.h>
#include <math.h>
#include <stdint.h>

#define S_IMG 2048
#define S_TXT 512
#define S_TOT 2560
#define DM    3072
#define NH    24
#define HD    128
#define ATOK  4
#define ADIM  1024
#define SM_SCALE 0.08838834764831845f  /* 1/sqrt(128) */

// ---------------- scratch (device globals; no allocation allowed) ----------------
__device__ float g_pq_img[(size_t)S_IMG * DM];
__device__ float g_pk_img[(size_t)S_IMG * DM];
__device__ float g_pv_img[(size_t)S_IMG * DM];
__device__ float g_pq_txt[(size_t)S_TXT * DM];
__device__ float g_pk_txt[(size_t)S_TXT * DM];
__device__ float g_pv_txt[(size_t)S_TXT * DM];
__device__ float g_q[(size_t)NH * S_TOT * HD];
__device__ float g_k[(size_t)NH * S_TOT * HD];
__device__ float g_v[(size_t)NH * S_TOT * HD];
__device__ __half g_hs[(size_t)S_TOT * DM];
__device__ float g_ka[ATOK * DM];
__device__ float g_va[ATOK * DM];
// fp16 copies. Activations: row-major [M,K]. Weights: TRANSPOSED [N,K].
__device__ __half g_chid[(size_t)S_IMG * DM];
__device__ __half g_cenc[(size_t)S_TXT * DM];
__device__ __half g_cad[ATOK * ADIM];
__device__ __half g_cWq[(size_t)DM * DM];
__device__ __half g_cWk[(size_t)DM * DM];
__device__ __half g_cWv[(size_t)DM * DM];
__device__ __half g_cWqa[(size_t)DM * DM];
__device__ __half g_cWka[(size_t)DM * DM];
__device__ __half g_cWva[(size_t)DM * DM];
__device__ __half g_cWo[(size_t)DM * DM];
__device__ __half g_cWoa[(size_t)DM * DM];
__device__ __half g_cWkad[(size_t)ADIM * DM]; /* [3072][1024] */
__device__ __half g_cWvad[(size_t)ADIM * DM];

// ------------------------- helpers ----------------------------------------------
__device__ __forceinline__ uint32_t f2tf32(float f) {
    uint32_t r;
    asm("cvt.rna.tf32.f32 %0, %1;" : "=r"(r) : "f"(f));
    return r;
}
__device__ __forceinline__ float tf32r(float f) { return __uint_as_float(f2tf32(f)); }
__device__ __forceinline__ void mma_tf32(float4& d, const uint32_t a[4],
                                         const uint32_t b[2]) {
    asm volatile(
        "mma.sync.aligned.m16n8k8.row.col.f32.tf32.tf32.f32 "
        "{%0,%1,%2,%3}, {%4,%5,%6,%7}, {%8,%9}, {%0,%1,%2,%3};\n"
        : "+f"(d.x), "+f"(d.y), "+f"(d.z), "+f"(d.w)
        : "r"(a[0]), "r"(a[1]), "r"(a[2]), "r"(a[3]), "r"(b[0]), "r"(b[1]));
}
__device__ __forceinline__ void mma_h16(float4& d, const uint32_t a[4],
                                        const uint32_t b[2]) {
    asm volatile(
        "mma.sync.aligned.m16n8k16.row.col.f32.f16.f16.f32 "
        "{%0,%1,%2,%3}, {%4,%5,%6,%7}, {%8,%9}, {%0,%1,%2,%3};\n"
        : "+f"(d.x), "+f"(d.y), "+f"(d.z), "+f"(d.w)
        : "r"(a[0]), "r"(a[1]), "r"(a[2]), "r"(a[3]), "r"(b[0]), "r"(b[1]));
}
#define CPA16(dst, src, pb) \
    asm volatile("cp.async.cg.shared.global [%0], [%1], 16, %2;\n" \
                 :: "r"(dst), "l"(src), "r"(pb))
#define CPCOMMIT() asm volatile("cp.async.commit_group;\n" ::)
#define CPWAIT(n)  asm volatile("cp.async.wait_group %0;\n" :: "n"(n))

// ------------------------- pre-convert passes ------------------------------------
struct CVH { const float* s; __half* d; int n; };
struct CVH3 { CVH e[3]; };
__global__ __launch_bounds__(256) void prep_cvt(CVH3 t)
{
    const CVH c = t.e[blockIdx.y];
    int idx = (blockIdx.x * 256 + threadIdx.x) * 4;
    if (idx < c.n) {
        float4 v = *(const float4*)&c.s[idx];
        *(__half2*)&c.d[idx]     = __floats2half2_rn(v.x, v.y);
        *(__half2*)&c.d[idx + 2] = __floats2half2_rn(v.z, v.w);
    }
}
// transpose [K,N] float -> [N,K] half
struct TP { const float* in; __half* out; int K; };
struct TP10 { TP e[10]; };
__global__ __launch_bounds__(256) void prep_tp(TP10 t)
{
    const TP p = t.e[blockIdx.z];
    const int k0 = blockIdx.y * 32, n0 = blockIdx.x * 32;
    if (k0 >= p.K) return;
    __shared__ float tile[32][33];
    const int tx = threadIdx.x & 31, ty = threadIdx.x >> 5;
    #pragma unroll
    for (int j = 0; j < 4; j++)
        tile[ty + j * 8][tx] = p.in[(size_t)(k0 + ty + j * 8) * DM + n0 + tx];
    __syncthreads();
    #pragma unroll
    for (int j = 0; j < 4; j++)
        p.out[(size_t)(n0 + ty + j * 8) * p.K + k0 + tx] =
            __float2half(tile[tx][ty + j * 8]);
}

// --------- batched cp.async fp16 GEMM: C[M,3072] = A[M,K] @ Wt[N,K]^T + bias -----
// 3-stage pipeline, CTA tile 128x128, BK=64 halves. A [M,K] half; Wt [N,K] half.
#define PH 72                       /* row pitch in halves; 36 words ≡ 4 mod 32 */
#define HSTAGE (2 * 128 * PH)       /* halves per stage (A+B) = 18432 */
#define HSMEM  (3 * HSTAGE * 2)     /* 110592 B */

struct GB { const __half* A; const __half* W; const float* bias; float* C;
            int M; int K; };
struct GB6 { GB e[6]; };

__global__ __launch_bounds__(256, 2) void gemm_h(GB6 ga)
{
    const GB g = ga.e[blockIdx.z];
    const int M = g.M, K = g.K;
    const int m0 = blockIdx.y * 128;
    if (m0 >= M) return;
    const int n0 = blockIdx.x * 128;

    extern __shared__ __half smh[];
    const __half* __restrict__ A = g.A;
    const __half* __restrict__ Wt = g.W;
    const int tid  = threadIdx.x;
    const int warp = tid >> 5, lane = tid & 31;
    const int gid  = lane >> 2, tig = lane & 3;
    const int wm = (warp & 3) * 32;
    const int wn = (warp >> 2) * 64;

    const int nIters = K / 64;

    auto issue_tile = [&](int it, int stage) {
        __half* As = smh + stage * HSTAGE;
        __half* Bs = As + 128 * PH;
        const int k0 = it * 64;
        // A tile: 128 rows x 64 halves = 1024 16B-chunks, 4/thread
        #pragma unroll
        for (int i = 0; i < 4; i++) {
            int c = tid + i * 256;
            int r = c >> 3, off = (c & 7) * 8;
            uint32_t dst = (uint32_t)__cvta_generic_to_shared(&As[r * PH + off]);
            const __half* src = &A[(size_t)(m0 + r) * K + k0 + off];
            CPA16(dst, src, (m0 + r < M) ? 16 : 0);
        }
        // B tile: 128 n-rows x 64 halves
        #pragma unroll
        for (int i = 0; i < 4; i++) {
            int c = tid + i * 256;
            int r = c >> 3, off = (c & 7) * 8;
            uint32_t dst = (uint32_t)__cvta_generic_to_shared(&Bs[r * PH + off]);
            const __half* src = &Wt[(size_t)(n0 + r) * K + k0 + off];
            CPA16(dst, src, 16);
        }
        CPCOMMIT();
    };

    float4 acc[2][8];
    #pragma unroll
    for (int i = 0; i < 2; i++)
        #pragma unroll
        for (int j = 0; j < 8; j++) acc[i][j] = make_float4(0.f, 0.f, 0.f, 0.f);

    issue_tile(0, 0);
    if (nIters > 1) issue_tile(1, 1);

    for (int it = 0; it < nIters; it++) {
        if (it + 1 < nIters) { CPWAIT(1); } else { CPWAIT(0); }
        __syncthreads();
        if (it + 2 < nIters) issue_tile(it + 2, (it + 2) % 3);

        const uint32_t* As32 = (const uint32_t*)(smh + (it % 3) * HSTAGE);
        const uint32_t* Bs32 = As32 + (128 * PH) / 2;   // 36 words per row
        #pragma unroll
        for (int ks = 0; ks < 4; ks++) {
            uint32_t af[2][4];
            #pragma unroll
            for (int mt = 0; mt < 2; mt++) {
                int base = (wm + mt * 16 + gid) * 36 + ks * 8 + tig;
                af[mt][0] = As32[base];
                af[mt][1] = As32[base + 8 * 36];
                af[mt][2] = As32[base + 4];
                af[mt][3] = As32[base + 8 * 36 + 4];
            }
            uint32_t bf[8][2];
            #pragma unroll
            for (int nt = 0; nt < 8; nt++) {
                int bb = (wn + nt * 8 + gid) * 36 + ks * 8 + tig;
                bf[nt][0] = Bs32[bb];
                bf[nt][1] = Bs32[bb + 4];
            }
            #pragma unroll
            for (int mt = 0; mt < 2; mt++)
                #pragma unroll
                for (int nt = 0; nt < 8; nt++)
                    mma_h16(acc[mt][nt], af[mt], bf[nt]);
        }
    }

    const float* bias = g.bias;
    float* C = g.C;
    #pragma unroll
    for (int mt = 0; mt < 2; mt++) {
        int r0 = m0 + wm + mt * 16 + gid;
        #pragma unroll
        for (int nt = 0; nt < 8; nt++) {
            int col = n0 + wn + nt * 8 + tig * 2;
            float b0 = bias ? bias[col] : 0.f;
            float b1 = bias ? bias[col + 1] : 0.f;
            if (r0 < M)
                *(float2*)&C[(size_t)r0 * DM + col] =
                    make_float2(acc[mt][nt].x + b0, acc[mt][nt].y + b1);
            if (r0 + 8 < M)
                *(float2*)&C[(size_t)(r0 + 8) * DM + col] =
                    make_float2(acc[mt][nt].z + b0, acc[mt][nt].w + b1);
        }
    }
}

// ------------- RMSNorm + RoPE -> tf32-rounded [H, S_TOT, HD] --------------------
// q is additionally pre-scaled by SM_SCALE.
__global__ __launch_bounds__(128) void qkv_transform(
    const float* __restrict__ nqw, const float* __restrict__ nkw,
    const float* __restrict__ naqw, const float* __restrict__ nakw,
    const float* __restrict__ fcos, const float* __restrict__ fsin)
{
    const int s = blockIdx.x, h = blockIdx.y, d = threadIdx.x;
    const int lane = d & 31, wid = d >> 5;
    __shared__ float ws[4];
    const bool txt = s < S_TXT;
    const size_t roff = txt ? (size_t)s * DM : (size_t)(s - S_TXT) * DM;
    const size_t col = roff + h * HD + d;
    const float* xq = txt ? g_pq_txt : g_pq_img;
    const float* xk = txt ? g_pk_txt : g_pk_img;
    const float* xv = txt ? g_pv_txt : g_pv_img;
    const float wq = txt ? naqw[d] : nqw[d];
    const float wk = txt ? nakw[d] : nkw[d];
    const float c = fcos[s * HD + d];
    const float sn = fsin[s * HD + d];
    const size_t oidx = ((size_t)h * S_TOT + s) * HD + d;

    float q = xq[col];
    float t2 = q * q;
    #pragma unroll
    for (int off = 16; off; off >>= 1) t2 += __shfl_xor_sync(0xffffffffu, t2, off);
    if (lane == 0) ws[wid] = t2;
    __syncthreads();
    float tot = ws[0] + ws[1] + ws[2] + ws[3];
    float qn = q * rsqrtf(tot * (1.f / HD) + 1e-6f) * wq;
    float pq = __shfl_xor_sync(0xffffffffu, qn, 1);
    float rotq = (d & 1) ? pq : -pq;
    g_q[oidx] = tf32r((qn * c + rotq * sn) * SM_SCALE);
    __syncthreads();

    float k = xk[col];
    t2 = k * k;
    #pragma unroll
    for (int off = 16; off; off >>= 1) t2 += __shfl_xor_sync(0xffffffffu, t2, off);
    if (lane == 0) ws[wid] = t2;
    __syncthreads();
    tot = ws[0] + ws[1] + ws[2] + ws[3];
    float kn = k * rsqrtf(tot * (1.f / HD) + 1e-6f) * wk;
    float pk = __shfl_xor_sync(0xffffffffu, kn, 1);
    float rotk = (d & 1) ? pk : -pk;
    g_k[oidx] = tf32r(kn * c + rotk * sn);

    g_v[oidx] = tf32r(xv[col]);
}

// ---------------- tensor-core flash attention, cp.async double-buffered ---------
// Fused epilogue: adapter 4-key cross-attention + merge -> writes g_hs (half).
#define AQ 128
#define AKV 64
#define QPAD 132
#define VPAD 136
#define OFF_K(st) (AQ * QPAD + (st) * (AKV * QPAD))
#define OFF_V(st) (AQ * QPAD + 2 * (AKV * QPAD) + (st) * (AKV * VPAD))
#define ATTN_SMEM ((AQ * QPAD + 2 * AKV * QPAD + 2 * AKV * VPAD) * 4)

__global__ __launch_bounds__(256) void attn_mma(const float* __restrict__ bscale)
{
    extern __shared__ float sm[];
    const int qt = blockIdx.x, h = blockIdx.y;
    const int tid = threadIdx.x;
    const int warp = tid >> 5, lane = tid & 31;
    const int gid = lane >> 2, tig = lane & 3;
    const int wm = warp * 16;

    const float* Qg = g_q + ((size_t)h * S_TOT + qt * AQ) * HD;
    const float* Kg = g_k + (size_t)h * S_TOT * HD;
    const float* Vg = g_v + (size_t)h * S_TOT * HD;

    auto issue_kv = [&](int kt, int st) {
        float* Ks = sm + OFF_K(st);
        float* Vs = sm + OFF_V(st);
        const float* Kt = Kg + (size_t)kt * AKV * HD;
        const float* Vt = Vg + (size_t)kt * AKV * HD;
        #pragma unroll
        for (int i = 0; i < 8; i++) {
            int c = tid + i * 256;
            int r = c >> 5, col = (c & 31) * 4;
            uint32_t dk = (uint32_t)__cvta_generic_to_shared(&Ks[r * QPAD + col]);
            CPA16(dk, &Kt[(size_t)r * HD + col], 16);
            uint32_t dv = (uint32_t)__cvta_generic_to_shared(&Vs[r * VPAD + col]);
            CPA16(dv, &Vt[(size_t)r * HD + col], 16);
        }
    };

    {
        #pragma unroll
        for (int i = 0; i < 16; i++) {
            int c = tid + i * 256;
            int r = c >> 5, col = (c & 31) * 4;
            uint32_t dq = (uint32_t)__cvta_generic_to_shared(&sm[r * QPAD + col]);
            CPA16(dq, &Qg[(size_t)r * HD + col], 16);
        }
        issue_kv(0, 0);
        CPCOMMIT();
    }

    float m0 = -1e30f, m1 = -1e30f, l0 = 0.f, l1 = 0.f;
    float4 o[16];
    #pragma unroll
    for (int i = 0; i < 16; i++) o[i] = make_float4(0.f, 0.f, 0.f, 0.f);

    const float* Qs = sm;
    for (int kt = 0; kt < S_TOT / AKV; kt++) {
        const int st = kt & 1;
        CPWAIT(0);
        __syncthreads();
        if (kt + 1 < S_TOT / AKV) { issue_kv(kt + 1, st ^ 1); CPCOMMIT(); }

        const float* Ks = sm + OFF_K(st);
        const float* Vs = sm + OFF_V(st);

        float4 s[8];
        #pragma unroll
        for (int nb = 0; nb < 8; nb++) s[nb] = make_float4(0.f, 0.f, 0.f, 0.f);
        #pragma unroll
        for (int ks = 0; ks < HD / 8; ks++) {
            const int kk = ks * 8;
            uint32_t a[4];
            a[0] = __float_as_uint(Qs[(wm + gid    ) * QPAD + kk + tig]);
            a[1] = __float_as_uint(Qs[(wm + gid + 8) * QPAD + kk + tig]);
            a[2] = __float_as_uint(Qs[(wm + gid    ) * QPAD + kk + tig + 4]);
            a[3] = __float_as_uint(Qs[(wm + gid + 8) * QPAD + kk + tig + 4]);
            #pragma unroll
            for (int nb = 0; nb < 8; nb++) {
                uint32_t b[2];
                b[0] = __float_as_uint(Ks[(nb * 8 + gid) * QPAD + kk + tig]);
                b[1] = __float_as_uint(Ks[(nb * 8 + gid) * QPAD + kk + tig + 4]);
                mma_tf32(s[nb], a, b);
            }
        }

        float mx0 = m0, mx1 = m1;
        #pragma unroll
        for (int nb = 0; nb < 8; nb++) {
            mx0 = fmaxf(mx0, fmaxf(s[nb].x, s[nb].y));
            mx1 = fmaxf(mx1, fmaxf(s[nb].z, s[nb].w));
        }
        mx0 = fmaxf(mx0, __shfl_xor_sync(0xffffffffu, mx0, 1));
        mx0 = fmaxf(mx0, __shfl_xor_sync(0xffffffffu, mx0, 2));
        mx1 = fmaxf(mx1, __shfl_xor_sync(0xffffffffu, mx1, 1));
        mx1 = fmaxf(mx1, __shfl_xor_sync(0xffffffffu, mx1, 2));
        const float c0 = __expf(m0 - mx0);
        const float c1 = __expf(m1 - mx1);
        m0 = mx0; m1 = mx1;
        float ls0 = 0.f, ls1 = 0.f;
        #pragma unroll
        for (int nb = 0; nb < 8; nb++) {
            s[nb].x = __expf(s[nb].x - m0);
            s[nb].y = __expf(s[nb].y - m0);
            s[nb].z = __expf(s[nb].z - m1);
            s[nb].w = __expf(s[nb].w - m1);
            ls0 += s[nb].x + s[nb].y;
            ls1 += s[nb].z + s[nb].w;
        }
        l0 = l0 * c0 + ls0;
        l1 = l1 * c1 + ls1;
        #pragma unroll
        for (int i = 0; i < 16; i++) {
            o[i].x *= c0; o[i].y *= c0; o[i].z *= c1; o[i].w *= c1;
        }

        const int srcA = (lane & ~3) | (tig >> 1);
        const int srcB = srcA + 2;
        #pragma unroll
        for (int kb = 0; kb < 8; kb++) {
            float xA = __shfl_sync(0xffffffffu, s[kb].x, srcA);
            float yA = __shfl_sync(0xffffffffu, s[kb].y, srcA);
            float zA = __shfl_sync(0xffffffffu, s[kb].z, srcA);
            float wA = __shfl_sync(0xffffffffu, s[kb].w, srcA);
            float xB = __shfl_sync(0xffffffffu, s[kb].x, srcB);
            float yB = __shfl_sync(0xffffffffu, s[kb].y, srcB);
            float zB = __shfl_sync(0xffffffffu, s[kb].z, srcB);
            float wB = __shfl_sync(0xffffffffu, s[kb].w, srcB);
            uint32_t a[4];
            a[0] = f2tf32((tig & 1) ? yA : xA);
            a[1] = f2tf32((tig & 1) ? wA : zA);
            a[2] = f2tf32((tig & 1) ? yB : xB);
            a[3] = f2tf32((tig & 1) ? wB : zB);
            #pragma unroll
            for (int nb = 0; nb < 16; nb++) {
                uint32_t b[2];
                b[0] = __float_as_uint(Vs[(kb * 8 + tig    ) * VPAD + nb * 8 + gid]);
                b[1] = __float_as_uint(Vs[(kb * 8 + tig + 4) * VPAD + nb * 8 + gid]);
                mma_tf32(o[nb], a, b);
            }
        }
    }

    l0 += __shfl_xor_sync(0xffffffffu, l0, 1);
    l0 += __shfl_xor_sync(0xffffffffu, l0, 2);
    l1 += __shfl_xor_sync(0xffffffffu, l1, 1);
    l1 += __shfl_xor_sync(0xffffffffu, l1, 2);
    const float i0 = 1.f / l0, i1 = 1.f / l1;

    // ---- fused adapter cross-attention (Qs resident; pre-scaled q) ----
    const int lr0 = wm + gid, lr1 = lr0 + 8;
    float sc0[ATOK], sc1[ATOK];
    #pragma unroll
    for (int t = 0; t < ATOK; t++) {
        const float* kap = &g_ka[t * DM + h * HD];
        float a0 = 0.f, a1 = 0.f;
        #pragma unroll
        for (int nb = 0; nb < 16; nb++) {
            int cc = nb * 8 + tig * 2;
            float k0v = kap[cc], k1v = kap[cc + 1];
            a0 += Qs[lr0 * QPAD + cc] * k0v + Qs[lr0 * QPAD + cc + 1] * k1v;
            a1 += Qs[lr1 * QPAD + cc] * k0v + Qs[lr1 * QPAD + cc + 1] * k1v;
        }
        a0 += __shfl_xor_sync(0xffffffffu, a0, 1);
        a0 += __shfl_xor_sync(0xffffffffu, a0, 2);
        a1 += __shfl_xor_sync(0xffffffffu, a1, 1);
        a1 += __shfl_xor_sync(0xffffffffu, a1, 2);
        sc0[t] = a0; sc1[t] = a1;
    }
    float w0[ATOK], w1[ATOK];
    {
        float mxa = fmaxf(fmaxf(sc0[0], sc0[1]), fmaxf(sc0[2], sc0[3]));
        float e0 = __expf(sc0[0] - mxa), e1 = __expf(sc0[1] - mxa);
        float e2 = __expf(sc0[2] - mxa), e3 = __expf(sc0[3] - mxa);
        float inv = 1.f / (e0 + e1 + e2 + e3);
        w0[0] = e0 * inv; w0[1] = e1 * inv; w0[2] = e2 * inv; w0[3] = e3 * inv;
    }
    {
        float mxa = fmaxf(fmaxf(sc1[0], sc1[1]), fmaxf(sc1[2], sc1[3]));
        float e0 = __expf(sc1[0] - mxa), e1 = __expf(sc1[1] - mxa);
        float e2 = __expf(sc1[2] - mxa), e3 = __expf(sc1[3] - mxa);
        float inv = 1.f / (e0 + e1 + e2 + e3);
        w1[0] = e0 * inv; w1[1] = e1 * inv; w1[2] = e2 * inv; w1[3] = e3 * inv;
    }
    const float bsc = bscale[0];

    const int s0 = qt * AQ + lr0;
    __half* H0 = g_hs + (size_t)s0 * DM + h * HD;
    __half* H1 = H0 + 8 * DM;
    #pragma unroll
    for (int nb = 0; nb < 16; nb++) {
        int cc = nb * 8 + tig * 2;
        int hcol = h * HD + cc;
        float va0a = g_va[0 * DM + hcol], va0b = g_va[0 * DM + hcol + 1];
        float va1a = g_va[1 * DM + hcol], va1b = g_va[1 * DM + hcol + 1];
        float va2a = g_va[2 * DM + hcol], va2b = g_va[2 * DM + hcol + 1];
        float va3a = g_va[3 * DM + hcol], va3b = g_va[3 * DM + hcol + 1];
        float vd0a = w0[0] * va0a + w0[1] * va1a + w0[2] * va2a + w0[3] * va3a;
        float vd0b = w0[0] * va0b + w0[1] * va1b + w0[2] * va2b + w0[3] * va3b;
        float vd1a = w1[0] * va0a + w1[1] * va1a + w1[2] * va2a + w1[3] * va3a;
        float vd1b = w1[0] * va0b + w1[1] * va1b + w1[2] * va2b + w1[3] * va3b;
        *(__half2*)&H0[cc] = __floats2half2_rn(o[nb].x * i0 + bsc * vd0a,
                                               o[nb].y * i0 + bsc * vd0b);
        *(__half2*)&H1[cc] = __floats2half2_rn(o[nb].z * i1 + bsc * vd1a,
                                               o[nb].w * i1 + bsc * vd1b);
    }
}

// -------------------------------- launch ---------------------------------------
extern "C" void kernel_launch(void* const* d_in, const int* in_sizes, int n_in,
                              void* d_out, int out_size)
{
    const float* hidden = (const float*)d_in[0];
    const float* enc    = (const float*)d_in[1];
    const float* adapt  = (const float*)d_in[2];
    const float* fcos   = (const float*)d_in[3];
    const float* fsin   = (const float*)d_in[4];
    const float* Wq  = (const float*)d_in[5];  const float* bq  = (const float*)d_in[6];
    const float* Wk  = (const float*)d_in[7];  const float* bk  = (const float*)d_in[8];
    const float* Wv  = (const float*)d_in[9];  const float* bv  = (const float*)d_in[10];
    const float* nqw = (const float*)d_in[11]; const float* nkw = (const float*)d_in[12];
    const float* Wqa = (const float*)d_in[13]; const float* bqa = (const float*)d_in[14];
    const float* Wka = (const float*)d_in[15]; const float* bka = (const float*)d_in[16];
    const float* Wva = (const float*)d_in[17]; const float* bva = (const float*)d_in[18];
    const float* naqw = (const float*)d_in[19]; const float* nakw = (const float*)d_in[20];
    const float* Wo  = (const float*)d_in[21]; const float* bo  = (const float*)d_in[22];
    const float* Woa = (const float*)d_in[23]; const float* boa = (const float*)d_in[24];
    const float* Wkad = (const float*)d_in[25]; const float* Wvad = (const float*)d_in[26];
    const float* bscale = (const float*)d_in[27];
    float* out = (float*)d_out;

    float *pq_img, *pk_img, *pv_img, *pq_txt, *pk_txt, *pv_txt, *ka, *va;
    __half *hs, *chid, *cenc, *cad, *cWq, *cWk, *cWv, *cWqa, *cWka, *cWva,
           *cWo, *cWoa, *cWkad, *cWvad;
    cudaGetSymbolAddress((void**)&pq_img, g_pq_img);
    cudaGetSymbolAddress((void**)&pk_img, g_pk_img);
    cudaGetSymbolAddress((void**)&pv_img, g_pv_img);
    cudaGetSymbolAddress((void**)&pq_txt, g_pq_txt);
    cudaGetSymbolAddress((void**)&pk_txt, g_pk_txt);
    cudaGetSymbolAddress((void**)&pv_txt, g_pv_txt);
    cudaGetSymbolAddress((void**)&ka, g_ka);
    cudaGetSymbolAddress((void**)&va, g_va);
    cudaGetSymbolAddress((void**)&hs, g_hs);
    cudaGetSymbolAddress((void**)&chid, g_chid);
    cudaGetSymbolAddress((void**)&cenc, g_cenc);
    cudaGetSymbolAddress((void**)&cad, g_cad);
    cudaGetSymbolAddress((void**)&cWq, g_cWq);
    cudaGetSymbolAddress((void**)&cWk, g_cWk);
    cudaGetSymbolAddress((void**)&cWv, g_cWv);
    cudaGetSymbolAddress((void**)&cWqa, g_cWqa);
    cudaGetSymbolAddress((void**)&cWka, g_cWka);
    cudaGetSymbolAddress((void**)&cWva, g_cWva);
    cudaGetSymbolAddress((void**)&cWo, g_cWo);
    cudaGetSymbolAddress((void**)&cWoa, g_cWoa);
    cudaGetSymbolAddress((void**)&cWkad, g_cWkad);
    cudaGetSymbolAddress((void**)&cWvad, g_cWvad);

    cudaFuncSetAttribute(attn_mma, cudaFuncAttributeMaxDynamicSharedMemorySize,
                         ATTN_SMEM);
    cudaFuncSetAttribute(gemm_h, cudaFuncAttributeMaxDynamicSharedMemorySize,
                         HSMEM);

    // --- convert activations to half; transpose+convert weights ---
    CVH3 cv;
    cv.e[0] = { hidden, chid, S_IMG * DM };
    cv.e[1] = { enc,    cenc, S_TXT * DM };
    cv.e[2] = { adapt,  cad,  ATOK * ADIM };
    prep_cvt<<<dim3((S_IMG * DM + 1023) / 1024, 3), 256>>>(cv);

    TP10 tp;
    tp.e[0] = { Wq,   cWq,   DM };
    tp.e[1] = { Wk,   cWk,   DM };
    tp.e[2] = { Wv,   cWv,   DM };
    tp.e[3] = { Wqa,  cWqa,  DM };
    tp.e[4] = { Wka,  cWka,  DM };
    tp.e[5] = { Wva,  cWva,  DM };
    tp.e[6] = { Wo,   cWo,   DM };
    tp.e[7] = { Woa,  cWoa,  DM };
    tp.e[8] = { Wkad, cWkad, ADIM };
    tp.e[9] = { Wvad, cWvad, ADIM };
    prep_tp<<<dim3(DM / 32, DM / 32, 10), 256>>>(tp);

    // --- all 6 QKV projections in one launch ---
    GB6 qkv;
    qkv.e[0] = { chid, cWq,  bq,  pq_img, S_IMG, DM };
    qkv.e[1] = { chid, cWk,  bk,  pk_img, S_IMG, DM };
    qkv.e[2] = { chid, cWv,  bv,  pv_img, S_IMG, DM };
    qkv.e[3] = { cenc, cWqa, bqa, pq_txt, S_TXT, DM };
    qkv.e[4] = { cenc, cWka, bka, pk_txt, S_TXT, DM };
    qkv.e[5] = { cenc, cWva, bva, pv_txt, S_TXT, DM };
    gemm_h<<<dim3(DM / 128, S_IMG / 128, 6), 256, HSMEM>>>(qkv);

    // --- adapter K/V (M=4, K=1024) ---
    GB6 ad;
    ad.e[0] = { cad, cWkad, (const float*)0, ka, ATOK, ADIM };
    ad.e[1] = { cad, cWvad, (const float*)0, va, ATOK, ADIM };
    ad.e[2] = ad.e[0]; ad.e[3] = ad.e[0]; ad.e[4] = ad.e[0]; ad.e[5] = ad.e[0];
    gemm_h<<<dim3(DM / 128, 1, 2), 256, HSMEM>>>(ad);

    // RMSNorm + RoPE + head layout (tf32-rounded, q pre-scaled)
    qkv_transform<<<dim3(S_TOT, NH), 128>>>(nqw, nkw, naqw, nakw, fcos, fsin);
    // joint flash attention + fused adapter merge -> g_hs (half)
    attn_mma<<<dim3(S_TOT / AQ, NH), 256, ATTN_SMEM>>>(bscale);

    // --- both output projections in one launch ---
    GB6 op;
    op.e[0] = { hs + (size_t)S_TXT * DM, cWo,  bo,  out,                      S_IMG, DM };
    op.e[1] = { hs,                      cWoa, boa, out + (size_t)S_IMG * DM, S_TXT, DM };
    op.e[2] = op.e[0]; op.e[3] = op.e[0]; op.e[4] = op.e[0]; op.e[5] = op.e[0];
    gemm_h<<<dim3(DM / 128, S_IMG / 128, 2), 256, HSMEM>>>(op);
}

// round 13
// speedup vs baseline: 1.6936x; 1.1604x over previous
#include <cuda_runtime.h>
#include <cuda_fp16.h>
#include <math.h>
#include <stdint.h>

#define S_IMG 2048
#define S_TXT 512
#define S_TOT 2560
#define DM    3072
#define NH    24
#define HD    128
#define ATOK  4
#define ADIM  1024
#define SM_SCALE 0.08838834764831845f  /* 1/sqrt(128) */

// ---------------- scratch (device globals; no allocation allowed) ----------------
__device__ float g_pq_img[(size_t)S_IMG * DM];
__device__ float g_pk_img[(size_t)S_IMG * DM];
__device__ float g_pv_img[(size_t)S_IMG * DM];
__device__ float g_pq_txt[(size_t)S_TXT * DM];
__device__ float g_pk_txt[(size_t)S_TXT * DM];
__device__ float g_pv_txt[(size_t)S_TXT * DM];
__device__ __half g_q[(size_t)NH * S_TOT * HD];
__device__ __half g_k[(size_t)NH * S_TOT * HD];
__device__ __half g_v[(size_t)NH * S_TOT * HD];
__device__ __half g_vt[(size_t)NH * HD * S_TOT];   /* [h][d][s] */
__device__ __half g_hs[(size_t)S_TOT * DM];
__device__ float g_ka[ATOK * DM];
__device__ float g_va[ATOK * DM];
// fp16 copies. Activations: row-major [M,K]. Weights: TRANSPOSED [N,K].
__device__ __half g_chid[(size_t)S_IMG * DM];
__device__ __half g_cenc[(size_t)S_TXT * DM];
__device__ __half g_cad[ATOK * ADIM];
__device__ __half g_cWq[(size_t)DM * DM];
__device__ __half g_cWk[(size_t)DM * DM];
__device__ __half g_cWv[(size_t)DM * DM];
__device__ __half g_cWqa[(size_t)DM * DM];
__device__ __half g_cWka[(size_t)DM * DM];
__device__ __half g_cWva[(size_t)DM * DM];
__device__ __half g_cWo[(size_t)DM * DM];
__device__ __half g_cWoa[(size_t)DM * DM];
__device__ __half g_cWkad[(size_t)ADIM * DM];
__device__ __half g_cWvad[(size_t)ADIM * DM];

// ------------------------- helpers ----------------------------------------------
__device__ __forceinline__ void mma_h16(float4& d, const uint32_t a[4],
                                        const uint32_t b[2]) {
    asm volatile(
        "mma.sync.aligned.m16n8k16.row.col.f32.f16.f16.f32 "
        "{%0,%1,%2,%3}, {%4,%5,%6,%7}, {%8,%9}, {%0,%1,%2,%3};\n"
        : "+f"(d.x), "+f"(d.y), "+f"(d.z), "+f"(d.w)
        : "r"(a[0]), "r"(a[1]), "r"(a[2]), "r"(a[3]), "r"(b[0]), "r"(b[1]));
}
__device__ __forceinline__ uint32_t packh2(float lo, float hi) {
    __half2 h = __floats2half2_rn(lo, hi);
    return *(uint32_t*)&h;
}
#define CPA16(dst, src, pb) \
    asm volatile("cp.async.cg.shared.global [%0], [%1], 16, %2;\n" \
                 :: "r"(dst), "l"(src), "r"(pb))
#define CPCOMMIT() asm volatile("cp.async.commit_group;\n" ::)
#define CPWAIT(n)  asm volatile("cp.async.wait_group %0;\n" :: "n"(n))

// ------------------------- pre-convert passes ------------------------------------
struct CVH { const float* s; __half* d; int n; };
struct CVH3 { CVH e[3]; };
__global__ __launch_bounds__(256) void prep_cvt(CVH3 t)
{
    const CVH c = t.e[blockIdx.y];
    int idx = (blockIdx.x * 256 + threadIdx.x) * 4;
    if (idx < c.n) {
        float4 v = *(const float4*)&c.s[idx];
        *(__half2*)&c.d[idx]     = __floats2half2_rn(v.x, v.y);
        *(__half2*)&c.d[idx + 2] = __floats2half2_rn(v.z, v.w);
    }
}
// transpose [K,N] float -> [N,K] half
struct TP { const float* in; __half* out; int K; };
struct TP10 { TP e[10]; };
__global__ __launch_bounds__(256) void prep_tp(TP10 t)
{
    const TP p = t.e[blockIdx.z];
    const int k0 = blockIdx.y * 32, n0 = blockIdx.x * 32;
    if (k0 >= p.K) return;
    __shared__ float tile[32][33];
    const int tx = threadIdx.x & 31, ty = threadIdx.x >> 5;
    #pragma unroll
    for (int j = 0; j < 4; j++)
        tile[ty + j * 8][tx] = p.in[(size_t)(k0 + ty + j * 8) * DM + n0 + tx];
    __syncthreads();
    #pragma unroll
    for (int j = 0; j < 4; j++)
        p.out[(size_t)(n0 + ty + j * 8) * p.K + k0 + tx] =
            __float2half(tile[tx][ty + j * 8]);
}
// transpose g_v [h][s][d] half -> g_vt [h][d][s] half
__global__ __launch_bounds__(256) void vtp()
{
    const int h = blockIdx.z;
    const int s0 = blockIdx.x * 32, d0 = blockIdx.y * 32;
    __shared__ __half tile[32][34];
    const int tx = threadIdx.x & 31, ty = threadIdx.x >> 5;
    const __half* src = g_v + (size_t)h * S_TOT * HD;
    __half* dst = g_vt + (size_t)h * HD * S_TOT;
    #pragma unroll
    for (int j = 0; j < 4; j++)
        tile[ty + j * 8][tx] = src[(size_t)(s0 + ty + j * 8) * HD + d0 + tx];
    __syncthreads();
    #pragma unroll
    for (int j = 0; j < 4; j++)
        dst[(size_t)(d0 + ty + j * 8) * S_TOT + s0 + tx] = tile[tx][ty + j * 8];
}

// --------- batched cp.async fp16 GEMM: C[M,3072] = A[M,K] @ Wt[N,K]^T + bias -----
// 3-stage pipeline, CTA tile 128x128, BK=64 halves. A [M,K] half; Wt [N,K] half.
#define PH 72                       /* row pitch in halves; 36 words ≡ 4 mod 32 */
#define HSTAGE (2 * 128 * PH)       /* halves per stage (A+B) = 18432 */
#define HSMEM  (3 * HSTAGE * 2)     /* 110592 B */

struct GB { const __half* A; const __half* W; const float* bias; float* C;
            int M; int K; };
struct GB6 { GB e[6]; };

__global__ __launch_bounds__(256, 2) void gemm_h(GB6 ga)
{
    const GB g = ga.e[blockIdx.z];
    const int M = g.M, K = g.K;
    const int m0 = blockIdx.y * 128;
    if (m0 >= M) return;
    const int n0 = blockIdx.x * 128;

    extern __shared__ __half smh[];
    const __half* __restrict__ A = g.A;
    const __half* __restrict__ Wt = g.W;
    const int tid  = threadIdx.x;
    const int warp = tid >> 5, lane = tid & 31;
    const int gid  = lane >> 2, tig = lane & 3;
    const int wm = (warp & 3) * 32;
    const int wn = (warp >> 2) * 64;

    const int nIters = K / 64;

    auto issue_tile = [&](int it, int stage) {
        __half* As = smh + stage * HSTAGE;
        __half* Bs = As + 128 * PH;
        const int k0 = it * 64;
        #pragma unroll
        for (int i = 0; i < 4; i++) {
            int c = tid + i * 256;
            int r = c >> 3, off = (c & 7) * 8;
            uint32_t dst = (uint32_t)__cvta_generic_to_shared(&As[r * PH + off]);
            const __half* src = &A[(size_t)(m0 + r) * K + k0 + off];
            CPA16(dst, src, (m0 + r < M) ? 16 : 0);
        }
        #pragma unroll
        for (int i = 0; i < 4; i++) {
            int c = tid + i * 256;
            int r = c >> 3, off = (c & 7) * 8;
            uint32_t dst = (uint32_t)__cvta_generic_to_shared(&Bs[r * PH + off]);
            const __half* src = &Wt[(size_t)(n0 + r) * K + k0 + off];
            CPA16(dst, src, 16);
        }
        CPCOMMIT();
    };

    float4 acc[2][8];
    #pragma unroll
    for (int i = 0; i < 2; i++)
        #pragma unroll
        for (int j = 0; j < 8; j++) acc[i][j] = make_float4(0.f, 0.f, 0.f, 0.f);

    issue_tile(0, 0);
    if (nIters > 1) issue_tile(1, 1);

    for (int it = 0; it < nIters; it++) {
        if (it + 1 < nIters) { CPWAIT(1); } else { CPWAIT(0); }
        __syncthreads();
        if (it + 2 < nIters) issue_tile(it + 2, (it + 2) % 3);

        const uint32_t* As32 = (const uint32_t*)(smh + (it % 3) * HSTAGE);
        const uint32_t* Bs32 = As32 + (128 * PH) / 2;
        #pragma unroll
        for (int ks = 0; ks < 4; ks++) {
            uint32_t af[2][4];
            #pragma unroll
            for (int mt = 0; mt < 2; mt++) {
                int base = (wm + mt * 16 + gid) * 36 + ks * 8 + tig;
                af[mt][0] = As32[base];
                af[mt][1] = As32[base + 8 * 36];
                af[mt][2] = As32[base + 4];
                af[mt][3] = As32[base + 8 * 36 + 4];
            }
            uint32_t bf[8][2];
            #pragma unroll
            for (int nt = 0; nt < 8; nt++) {
                int bb = (wn + nt * 8 + gid) * 36 + ks * 8 + tig;
                bf[nt][0] = Bs32[bb];
                bf[nt][1] = Bs32[bb + 4];
            }
            #pragma unroll
            for (int mt = 0; mt < 2; mt++)
                #pragma unroll
                for (int nt = 0; nt < 8; nt++)
                    mma_h16(acc[mt][nt], af[mt], bf[nt]);
        }
    }

    const float* bias = g.bias;
    float* C = g.C;
    #pragma unroll
    for (int mt = 0; mt < 2; mt++) {
        int r0 = m0 + wm + mt * 16 + gid;
        #pragma unroll
        for (int nt = 0; nt < 8; nt++) {
            int col = n0 + wn + nt * 8 + tig * 2;
            float b0 = bias ? bias[col] : 0.f;
            float b1 = bias ? bias[col + 1] : 0.f;
            if (r0 < M)
                *(float2*)&C[(size_t)r0 * DM + col] =
                    make_float2(acc[mt][nt].x + b0, acc[mt][nt].y + b1);
            if (r0 + 8 < M)
                *(float2*)&C[(size_t)(r0 + 8) * DM + col] =
                    make_float2(acc[mt][nt].z + b0, acc[mt][nt].w + b1);
        }
    }
}

// ------------- RMSNorm + RoPE -> fp16 [H, S_TOT, HD] ----------------------------
// q is additionally pre-scaled by SM_SCALE.
__global__ __launch_bounds__(128) void qkv_transform(
    const float* __restrict__ nqw, const float* __restrict__ nkw,
    const float* __restrict__ naqw, const float* __restrict__ nakw,
    const float* __restrict__ fcos, const float* __restrict__ fsin)
{
    const int s = blockIdx.x, h = blockIdx.y, d = threadIdx.x;
    const int lane = d & 31, wid = d >> 5;
    __shared__ float ws[4];
    const bool txt = s < S_TXT;
    const size_t roff = txt ? (size_t)s * DM : (size_t)(s - S_TXT) * DM;
    const size_t col = roff + h * HD + d;
    const float* xq = txt ? g_pq_txt : g_pq_img;
    const float* xk = txt ? g_pk_txt : g_pk_img;
    const float* xv = txt ? g_pv_txt : g_pv_img;
    const float wq = txt ? naqw[d] : nqw[d];
    const float wk = txt ? nakw[d] : nkw[d];
    const float c = fcos[s * HD + d];
    const float sn = fsin[s * HD + d];
    const size_t oidx = ((size_t)h * S_TOT + s) * HD + d;

    float q = xq[col];
    float t2 = q * q;
    #pragma unroll
    for (int off = 16; off; off >>= 1) t2 += __shfl_xor_sync(0xffffffffu, t2, off);
    if (lane == 0) ws[wid] = t2;
    __syncthreads();
    float tot = ws[0] + ws[1] + ws[2] + ws[3];
    float qn = q * rsqrtf(tot * (1.f / HD) + 1e-6f) * wq;
    float pq = __shfl_xor_sync(0xffffffffu, qn, 1);
    float rotq = (d & 1) ? pq : -pq;
    g_q[oidx] = __float2half((qn * c + rotq * sn) * SM_SCALE);
    __syncthreads();

    float k = xk[col];
    t2 = k * k;
    #pragma unroll
    for (int off = 16; off; off >>= 1) t2 += __shfl_xor_sync(0xffffffffu, t2, off);
    if (lane == 0) ws[wid] = t2;
    __syncthreads();
    tot = ws[0] + ws[1] + ws[2] + ws[3];
    float kn = k * rsqrtf(tot * (1.f / HD) + 1e-6f) * wk;
    float pk = __shfl_xor_sync(0xffffffffu, kn, 1);
    float rotk = (d & 1) ? pk : -pk;
    g_k[oidx] = __float2half(kn * c + rotk * sn);

    g_v[oidx] = __float2half(xv[col]);
}

// ---------------- fp16 tensor-core flash attention, cp.async double-buffered -----
// Fused epilogue: adapter 4-key cross-attention + merge -> writes g_hs (half).
#define AQ 128
#define AKV 64
#define QP 136               /* Q/K row pitch (halves); 68 words ≡ 4 mod 32 */
#define VP 72                /* Vt row pitch (halves); 36 words ≡ 4 mod 32 */
#define HOFF_Q 0
#define HOFF_K(st) (AQ * QP + (st) * (AKV * QP))
#define HOFF_V(st) (AQ * QP + 2 * (AKV * QP) + (st) * (HD * VP))
#define ATTN_SMEM ((AQ * QP + 2 * AKV * QP + 2 * HD * VP) * 2)

__global__ __launch_bounds__(256) void attn_mma(const float* __restrict__ bscale)
{
    extern __shared__ __half smah[];
    const int qt = blockIdx.x, h = blockIdx.y;
    const int tid = threadIdx.x;
    const int warp = tid >> 5, lane = tid & 31;
    const int gid = lane >> 2, tig = lane & 3;
    const int wm = warp * 16;

    const __half* Qg = g_q + ((size_t)h * S_TOT + qt * AQ) * HD;
    const __half* Kg = g_k + (size_t)h * S_TOT * HD;
    const __half* Vtg = g_vt + (size_t)h * HD * S_TOT;

    auto issue_kv = [&](int kt, int st) {
        __half* Ks = smah + HOFF_K(st);
        __half* Vs = smah + HOFF_V(st);
        const __half* Kt = Kg + (size_t)kt * AKV * HD;
        // K tile: 64 rows x 128 halves = 1024 chunks
        #pragma unroll
        for (int i = 0; i < 4; i++) {
            int c = tid + i * 256;
            int r = c >> 4, col = (c & 15) * 8;
            uint32_t dk = (uint32_t)__cvta_generic_to_shared(&Ks[r * QP + col]);
            CPA16(dk, &Kt[(size_t)r * HD + col], 16);
        }
        // Vt tile: 128 d-rows x 64 halves = 1024 chunks
        #pragma unroll
        for (int i = 0; i < 4; i++) {
            int c = tid + i * 256;
            int r = c >> 3, col = (c & 7) * 8;
            uint32_t dv = (uint32_t)__cvta_generic_to_shared(&Vs[r * VP + col]);
            CPA16(dv, &Vtg[(size_t)r * S_TOT + kt * AKV + col], 16);
        }
    };

    // prologue: Q + KV tile 0 in one group
    {
        #pragma unroll
        for (int i = 0; i < 8; i++) {
            int c = tid + i * 256;               // 2048 chunks
            int r = c >> 4, col = (c & 15) * 8;
            uint32_t dq = (uint32_t)__cvta_generic_to_shared(&smah[r * QP + col]);
            CPA16(dq, &Qg[(size_t)r * HD + col], 16);
        }
        issue_kv(0, 0);
        CPCOMMIT();
    }

    float m0 = -1e30f, m1 = -1e30f, l0 = 0.f, l1 = 0.f;
    float4 o[16];
    #pragma unroll
    for (int i = 0; i < 16; i++) o[i] = make_float4(0.f, 0.f, 0.f, 0.f);

    const uint32_t* Qw = (const uint32_t*)smah;
    for (int kt = 0; kt < S_TOT / AKV; kt++) {
        const int st = kt & 1;
        CPWAIT(0);
        __syncthreads();
        if (kt + 1 < S_TOT / AKV) { issue_kv(kt + 1, st ^ 1); CPCOMMIT(); }

        const uint32_t* Kw = (const uint32_t*)(smah + HOFF_K(st));
        const uint32_t* Vw = (const uint32_t*)(smah + HOFF_V(st));

        // S = Q @ K^T : 16 x 64 per warp (fp16 k16)
        float4 s[8];
        #pragma unroll
        for (int nb = 0; nb < 8; nb++) s[nb] = make_float4(0.f, 0.f, 0.f, 0.f);
        #pragma unroll
        for (int ks = 0; ks < HD / 16; ks++) {
            uint32_t a[4];
            int qb = (wm + gid) * 68 + ks * 8 + tig;
            a[0] = Qw[qb];
            a[1] = Qw[qb + 8 * 68];
            a[2] = Qw[qb + 4];
            a[3] = Qw[qb + 8 * 68 + 4];
            #pragma unroll
            for (int nb = 0; nb < 8; nb++) {
                uint32_t b[2];
                int kb = (nb * 8 + gid) * 68 + ks * 8 + tig;
                b[0] = Kw[kb];
                b[1] = Kw[kb + 4];
                mma_h16(s[nb], a, b);
            }
        }

        // online softmax
        float mx0 = m0, mx1 = m1;
        #pragma unroll
        for (int nb = 0; nb < 8; nb++) {
            mx0 = fmaxf(mx0, fmaxf(s[nb].x, s[nb].y));
            mx1 = fmaxf(mx1, fmaxf(s[nb].z, s[nb].w));
        }
        mx0 = fmaxf(mx0, __shfl_xor_sync(0xffffffffu, mx0, 1));
        mx0 = fmaxf(mx0, __shfl_xor_sync(0xffffffffu, mx0, 2));
        mx1 = fmaxf(mx1, __shfl_xor_sync(0xffffffffu, mx1, 1));
        mx1 = fmaxf(mx1, __shfl_xor_sync(0xffffffffu, mx1, 2));
        const float c0 = __expf(m0 - mx0);
        const float c1 = __expf(m1 - mx1);
        m0 = mx0; m1 = mx1;
        float ls0 = 0.f, ls1 = 0.f;
        #pragma unroll
        for (int nb = 0; nb < 8; nb++) {
            s[nb].x = __expf(s[nb].x - m0);
            s[nb].y = __expf(s[nb].y - m0);
            s[nb].z = __expf(s[nb].z - m1);
            s[nb].w = __expf(s[nb].w - m1);
            ls0 += s[nb].x + s[nb].y;
            ls1 += s[nb].z + s[nb].w;
        }
        l0 = l0 * c0 + ls0;
        l1 = l1 * c1 + ls1;
        #pragma unroll
        for (int i = 0; i < 16; i++) {
            o[i].x *= c0; o[i].y *= c0; o[i].z *= c1; o[i].w *= c1;
        }

        // O += P @ V^T tiles. P A-frags come straight from S C-frags (no shuffles).
        #pragma unroll
        for (int ks = 0; ks < 4; ks++) {
            uint32_t a[4];
            a[0] = packh2(s[2 * ks].x,     s[2 * ks].y);
            a[1] = packh2(s[2 * ks].z,     s[2 * ks].w);
            a[2] = packh2(s[2 * ks + 1].x, s[2 * ks + 1].y);
            a[3] = packh2(s[2 * ks + 1].z, s[2 * ks + 1].w);
            #pragma unroll
            for (int nb = 0; nb < 16; nb++) {
                uint32_t b[2];
                int vb = (nb * 8 + gid) * 36 + ks * 8 + tig;
                b[0] = Vw[vb];
                b[1] = Vw[vb + 4];
                mma_h16(o[nb], a, b);
            }
        }
    }

    l0 += __shfl_xor_sync(0xffffffffu, l0, 1);
    l0 += __shfl_xor_sync(0xffffffffu, l0, 2);
    l1 += __shfl_xor_sync(0xffffffffu, l1, 1);
    l1 += __shfl_xor_sync(0xffffffffu, l1, 2);
    const float i0 = 1.f / l0, i1 = 1.f / l1;

    // ---- fused adapter cross-attention (Qs resident in smem; pre-scaled q) ----
    const int lr0 = wm + gid, lr1 = lr0 + 8;
    float sc0[ATOK], sc1[ATOK];
    #pragma unroll
    for (int t = 0; t < ATOK; t++) {
        const float* kap = &g_ka[t * DM + h * HD];
        float a0 = 0.f, a1 = 0.f;
        #pragma unroll
        for (int nb = 0; nb < 16; nb++) {
            int cc = nb * 8 + tig * 2;
            float k0v = kap[cc], k1v = kap[cc + 1];
            float2 q0 = __half22float2(*(const __half2*)&smah[lr0 * QP + cc]);
            float2 q1 = __half22float2(*(const __half2*)&smah[lr1 * QP + cc]);
            a0 += q0.x * k0v + q0.y * k1v;
            a1 += q1.x * k0v + q1.y * k1v;
        }
        a0 += __shfl_xor_sync(0xffffffffu, a0, 1);
        a0 += __shfl_xor_sync(0xffffffffu, a0, 2);
        a1 += __shfl_xor_sync(0xffffffffu, a1, 1);
        a1 += __shfl_xor_sync(0xffffffffu, a1, 2);
        sc0[t] = a0; sc1[t] = a1;
    }
    float w0[ATOK], w1[ATOK];
    {
        float mxa = fmaxf(fmaxf(sc0[0], sc0[1]), fmaxf(sc0[2], sc0[3]));
        float e0 = __expf(sc0[0] - mxa), e1 = __expf(sc0[1] - mxa);
        float e2 = __expf(sc0[2] - mxa), e3 = __expf(sc0[3] - mxa);
        float inv = 1.f / (e0 + e1 + e2 + e3);
        w0[0] = e0 * inv; w0[1] = e1 * inv; w0[2] = e2 * inv; w0[3] = e3 * inv;
    }
    {
        float mxa = fmaxf(fmaxf(sc1[0], sc1[1]), fmaxf(sc1[2], sc1[3]));
        float e0 = __expf(sc1[0] - mxa), e1 = __expf(sc1[1] - mxa);
        float e2 = __expf(sc1[2] - mxa), e3 = __expf(sc1[3] - mxa);
        float inv = 1.f / (e0 + e1 + e2 + e3);
        w1[0] = e0 * inv; w1[1] = e1 * inv; w1[2] = e2 * inv; w1[3] = e3 * inv;
    }
    const float bsc = bscale[0];

    const int s0 = qt * AQ + lr0;
    __half* H0 = g_hs + (size_t)s0 * DM + h * HD;
    __half* H1 = H0 + 8 * DM;
    #pragma unroll
    for (int nb = 0; nb < 16; nb++) {
        int cc = nb * 8 + tig * 2;
        int hcol = h * HD + cc;
        float va0a = g_va[0 * DM + hcol], va0b = g_va[0 * DM + hcol + 1];
        float va1a = g_va[1 * DM + hcol], va1b = g_va[1 * DM + hcol + 1];
        float va2a = g_va[2 * DM + hcol], va2b = g_va[2 * DM + hcol + 1];
        float va3a = g_va[3 * DM + hcol], va3b = g_va[3 * DM + hcol + 1];
        float vd0a = w0[0] * va0a + w0[1] * va1a + w0[2] * va2a + w0[3] * va3a;
        float vd0b = w0[0] * va0b + w0[1] * va1b + w0[2] * va2b + w0[3] * va3b;
        float vd1a = w1[0] * va0a + w1[1] * va1a + w1[2] * va2a + w1[3] * va3a;
        float vd1b = w1[0] * va0b + w1[1] * va1b + w1[2] * va2b + w1[3] * va3b;
        *(__half2*)&H0[cc] = __floats2half2_rn(o[nb].x * i0 + bsc * vd0a,
                                               o[nb].y * i0 + bsc * vd0b);
        *(__half2*)&H1[cc] = __floats2half2_rn(o[nb].z * i1 + bsc * vd1a,
                                               o[nb].w * i1 + bsc * vd1b);
    }
}

// -------------------------------- launch ---------------------------------------
extern "C" void kernel_launch(void* const* d_in, const int* in_sizes, int n_in,
                              void* d_out, int out_size)
{
    const float* hidden = (const float*)d_in[0];
    const float* enc    = (const float*)d_in[1];
    const float* adapt  = (const float*)d_in[2];
    const float* fcos   = (const float*)d_in[3];
    const float* fsin   = (const float*)d_in[4];
    const float* Wq  = (const float*)d_in[5];  const float* bq  = (const float*)d_in[6];
    const float* Wk  = (const float*)d_in[7];  const float* bk  = (const float*)d_in[8];
    const float* Wv  = (const float*)d_in[9];  const float* bv  = (const float*)d_in[10];
    const float* nqw = (const float*)d_in[11]; const float* nkw = (const float*)d_in[12];
    const float* Wqa = (const float*)d_in[13]; const float* bqa = (const float*)d_in[14];
    const float* Wka = (const float*)d_in[15]; const float* bka = (const float*)d_in[16];
    const float* Wva = (const float*)d_in[17]; const float* bva = (const float*)d_in[18];
    const float* naqw = (const float*)d_in[19]; const float* nakw = (const float*)d_in[20];
    const float* Wo  = (const float*)d_in[21]; const float* bo  = (const float*)d_in[22];
    const float* Woa = (const float*)d_in[23]; const float* boa = (const float*)d_in[24];
    const float* Wkad = (const float*)d_in[25]; const float* Wvad = (const float*)d_in[26];
    const float* bscale = (const float*)d_in[27];
    float* out = (float*)d_out;

    float *pq_img, *pk_img, *pv_img, *pq_txt, *pk_txt, *pv_txt, *ka, *va;
    __half *hs, *chid, *cenc, *cad, *cWq, *cWk, *cWv, *cWqa, *cWka, *cWva,
           *cWo, *cWoa, *cWkad, *cWvad;
    cudaGetSymbolAddress((void**)&pq_img, g_pq_img);
    cudaGetSymbolAddress((void**)&pk_img, g_pk_img);
    cudaGetSymbolAddress((void**)&pv_img, g_pv_img);
    cudaGetSymbolAddress((void**)&pq_txt, g_pq_txt);
    cudaGetSymbolAddress((void**)&pk_txt, g_pk_txt);
    cudaGetSymbolAddress((void**)&pv_txt, g_pv_txt);
    cudaGetSymbolAddress((void**)&ka, g_ka);
    cudaGetSymbolAddress((void**)&va, g_va);
    cudaGetSymbolAddress((void**)&hs, g_hs);
    cudaGetSymbolAddress((void**)&chid, g_chid);
    cudaGetSymbolAddress((void**)&cenc, g_cenc);
    cudaGetSymbolAddress((void**)&cad, g_cad);
    cudaGetSymbolAddress((void**)&cWq, g_cWq);
    cudaGetSymbolAddress((void**)&cWk, g_cWk);
    cudaGetSymbolAddress((void**)&cWv, g_cWv);
    cudaGetSymbolAddress((void**)&cWqa, g_cWqa);
    cudaGetSymbolAddress((void**)&cWka, g_cWka);
    cudaGetSymbolAddress((void**)&cWva, g_cWva);
    cudaGetSymbolAddress((void**)&cWo, g_cWo);
    cudaGetSymbolAddress((void**)&cWoa, g_cWoa);
    cudaGetSymbolAddress((void**)&cWkad, g_cWkad);
    cudaGetSymbolAddress((void**)&cWvad, g_cWvad);

    cudaFuncSetAttribute(attn_mma, cudaFuncAttributeMaxDynamicSharedMemorySize,
                         ATTN_SMEM);
    cudaFuncSetAttribute(gemm_h, cudaFuncAttributeMaxDynamicSharedMemorySize,
                         HSMEM);

    // --- convert activations to half; transpose+convert weights ---
    CVH3 cv;
    cv.e[0] = { hidden, chid, S_IMG * DM };
    cv.e[1] = { enc,    cenc, S_TXT * DM };
    cv.e[2] = { adapt,  cad,  ATOK * ADIM };
    prep_cvt<<<dim3((S_IMG * DM + 1023) / 1024, 3), 256>>>(cv);

    TP10 tp;
    tp.e[0] = { Wq,   cWq,   DM };
    tp.e[1] = { Wk,   cWk,   DM };
    tp.e[2] = { Wv,   cWv,   DM };
    tp.e[3] = { Wqa,  cWqa,  DM };
    tp.e[4] = { Wka,  cWka,  DM };
    tp.e[5] = { Wva,  cWva,  DM };
    tp.e[6] = { Wo,   cWo,   DM };
    tp.e[7] = { Woa,  cWoa,  DM };
    tp.e[8] = { Wkad, cWkad, ADIM };
    tp.e[9] = { Wvad, cWvad, ADIM };
    prep_tp<<<dim3(DM / 32, DM / 32, 10), 256>>>(tp);

    // --- all 6 QKV projections in one launch ---
    GB6 qkv;
    qkv.e[0] = { chid, cWq,  bq,  pq_img, S_IMG, DM };
    qkv.e[1] = { chid, cWk,  bk,  pk_img, S_IMG, DM };
    qkv.e[2] = { chid, cWv,  bv,  pv_img, S_IMG, DM };
    qkv.e[3] = { cenc, cWqa, bqa, pq_txt, S_TXT, DM };
    qkv.e[4] = { cenc, cWka, bka, pk_txt, S_TXT, DM };
    qkv.e[5] = { cenc, cWva, bva, pv_txt, S_TXT, DM };
    gemm_h<<<dim3(DM / 128, S_IMG / 128, 6), 256, HSMEM>>>(qkv);

    // --- adapter K/V (M=4, K=1024) ---
    GB6 ad;
    ad.e[0] = { cad, cWkad, (const float*)0, ka, ATOK, ADIM };
    ad.e[1] = { cad, cWvad, (const float*)0, va, ATOK, ADIM };
    ad.e[2] = ad.e[0]; ad.e[3] = ad.e[0]; ad.e[4] = ad.e[0]; ad.e[5] = ad.e[0];
    gemm_h<<<dim3(DM / 128, 1, 2), 256, HSMEM>>>(ad);

    // RMSNorm + RoPE + head layout (fp16 out, q pre-scaled)
    qkv_transform<<<dim3(S_TOT, NH), 128>>>(nqw, nkw, naqw, nakw, fcos, fsin);
    // V transpose for fp16 PV mma
    vtp<<<dim3(S_TOT / 32, HD / 32, NH), 256>>>();
    // joint flash attention + fused adapter merge -> g_hs (half)
    attn_mma<<<dim3(S_TOT / AQ, NH), 256, ATTN_SMEM>>>(bscale);

    // --- both output projections in one launch ---
    GB6 op;
    op.e[0] = { hs + (size_t)S_TXT * DM, cWo,  bo,  out,                      S_IMG, DM };
    op.e[1] = { hs,                      cWoa, boa, out + (size_t)S_IMG * DM, S_TXT, DM };
    op.e[2] = op.e[0]; op.e[3] = op.e[0]; op.e[4] = op.e[0]; op.e[5] = op.e[0];
    gemm_h<<<dim3(DM / 128, S_IMG / 128, 2), 256, HSMEM>>>(op);
}

// round 14
// speedup vs baseline: 1.7846x; 1.0537x over previous
#include <cuda_runtime.h>
#include <cuda_fp16.h>
#include <math.h>
#include <stdint.h>

#define S_IMG 2048
#define S_TXT 512
#define S_TOT 2560
#define DM    3072
#define NH    24
#define HD    128
#define ATOK  4
#define ADIM  1024
#define SM_SCALE 0.08838834764831845f  /* 1/sqrt(128) */

// ---------------- scratch (device globals; no allocation allowed) ----------------
__device__ float g_pq_img[(size_t)S_IMG * DM];
__device__ float g_pk_img[(size_t)S_IMG * DM];
__device__ float g_pv_img[(size_t)S_IMG * DM];
__device__ float g_pq_txt[(size_t)S_TXT * DM];
__device__ float g_pk_txt[(size_t)S_TXT * DM];
__device__ float g_pv_txt[(size_t)S_TXT * DM];
__device__ __half g_q[(size_t)NH * S_TOT * HD];
__device__ __half g_k[(size_t)NH * S_TOT * HD];
__device__ __half g_v[(size_t)NH * S_TOT * HD];
__device__ __half g_vt[(size_t)NH * HD * S_TOT];   /* [h][d][s] */
__device__ __half g_hs[(size_t)S_TOT * DM];
__device__ float g_ka[ATOK * DM];
__device__ float g_va[ATOK * DM];
// fp16 copies. Activations: row-major [M,K]. Weights: TRANSPOSED [N,K].
__device__ __half g_chid[(size_t)S_IMG * DM];
__device__ __half g_cenc[(size_t)S_TXT * DM];
__device__ __half g_cad[ATOK * ADIM];
__device__ __half g_cWq[(size_t)DM * DM];
__device__ __half g_cWk[(size_t)DM * DM];
__device__ __half g_cWv[(size_t)DM * DM];
__device__ __half g_cWqa[(size_t)DM * DM];
__device__ __half g_cWka[(size_t)DM * DM];
__device__ __half g_cWva[(size_t)DM * DM];
__device__ __half g_cWo[(size_t)DM * DM];
__device__ __half g_cWoa[(size_t)DM * DM];
__device__ __half g_cWkad[(size_t)ADIM * DM];
__device__ __half g_cWvad[(size_t)ADIM * DM];

// ------------------------- helpers ----------------------------------------------
__device__ __forceinline__ void mma_h16(float4& d, const uint32_t a[4],
                                        const uint32_t b[2]) {
    asm volatile(
        "mma.sync.aligned.m16n8k16.row.col.f32.f16.f16.f32 "
        "{%0,%1,%2,%3}, {%4,%5,%6,%7}, {%8,%9}, {%0,%1,%2,%3};\n"
        : "+f"(d.x), "+f"(d.y), "+f"(d.z), "+f"(d.w)
        : "r"(a[0]), "r"(a[1]), "r"(a[2]), "r"(a[3]), "r"(b[0]), "r"(b[1]));
}
__device__ __forceinline__ void ldmx4(uint32_t& r0, uint32_t& r1, uint32_t& r2,
                                      uint32_t& r3, uint32_t addr) {
    asm volatile("ldmatrix.sync.aligned.m8n8.x4.shared.b16 {%0,%1,%2,%3}, [%4];"
                 : "=r"(r0), "=r"(r1), "=r"(r2), "=r"(r3) : "r"(addr));
}
__device__ __forceinline__ uint32_t packh2(float lo, float hi) {
    __half2 h = __floats2half2_rn(lo, hi);
    return *(uint32_t*)&h;
}
#define CPA16(dst, src, pb) \
    asm volatile("cp.async.cg.shared.global [%0], [%1], 16, %2;\n" \
                 :: "r"(dst), "l"(src), "r"(pb))
#define CPCOMMIT() asm volatile("cp.async.commit_group;\n" ::)
#define CPWAIT(n)  asm volatile("cp.async.wait_group %0;\n" :: "n"(n))

// ------------------------- pre-convert passes ------------------------------------
struct CVH { const float* s; __half* d; int n; };
struct CVH3 { CVH e[3]; };
__global__ __launch_bounds__(256) void prep_cvt(CVH3 t)
{
    const CVH c = t.e[blockIdx.y];
    int idx = (blockIdx.x * 256 + threadIdx.x) * 4;
    if (idx < c.n) {
        float4 v = *(const float4*)&c.s[idx];
        *(__half2*)&c.d[idx]     = __floats2half2_rn(v.x, v.y);
        *(__half2*)&c.d[idx + 2] = __floats2half2_rn(v.z, v.w);
    }
}
// transpose [K,N] float -> [N,K] half
struct TP { const float* in; __half* out; int K; };
struct TP10 { TP e[10]; };
__global__ __launch_bounds__(256) void prep_tp(TP10 t)
{
    const TP p = t.e[blockIdx.z];
    const int k0 = blockIdx.y * 32, n0 = blockIdx.x * 32;
    if (k0 >= p.K) return;
    __shared__ float tile[32][33];
    const int tx = threadIdx.x & 31, ty = threadIdx.x >> 5;
    #pragma unroll
    for (int j = 0; j < 4; j++)
        tile[ty + j * 8][tx] = p.in[(size_t)(k0 + ty + j * 8) * DM + n0 + tx];
    __syncthreads();
    #pragma unroll
    for (int j = 0; j < 4; j++)
        p.out[(size_t)(n0 + ty + j * 8) * p.K + k0 + tx] =
            __float2half(tile[tx][ty + j * 8]);
}
// transpose g_v [h][s][d] half -> g_vt [h][d][s] half
__global__ __launch_bounds__(256) void vtp()
{
    const int h = blockIdx.z;
    const int s0 = blockIdx.x * 32, d0 = blockIdx.y * 32;
    __shared__ __half tile[32][34];
    const int tx = threadIdx.x & 31, ty = threadIdx.x >> 5;
    const __half* src = g_v + (size_t)h * S_TOT * HD;
    __half* dst = g_vt + (size_t)h * HD * S_TOT;
    #pragma unroll
    for (int j = 0; j < 4; j++)
        tile[ty + j * 8][tx] = src[(size_t)(s0 + ty + j * 8) * HD + d0 + tx];
    __syncthreads();
    #pragma unroll
    for (int j = 0; j < 4; j++)
        dst[(size_t)(d0 + ty + j * 8) * S_TOT + s0 + tx] = tile[tx][ty + j * 8];
}

// --------- batched cp.async fp16 GEMM: C[M,3072] = A[M,K] @ Wt[N,K]^T + bias -----
// 3-stage pipeline, CTA tile 128x128, BK=64 halves, ldmatrix fragment loads.
#define PH 72                       /* row pitch in halves; 36 words ≡ 4 mod 32 */
#define HSTAGE (2 * 128 * PH)       /* halves per stage (A+B) = 18432 */
#define HSMEM  (3 * HSTAGE * 2)     /* 110592 B */

struct GB { const __half* A; const __half* W; const float* bias; float* C;
            int M; int K; };
struct GB6 { GB e[6]; };

__global__ __launch_bounds__(256, 2) void gemm_h(GB6 ga)
{
    const GB g = ga.e[blockIdx.z];
    const int M = g.M, K = g.K;
    const int m0 = blockIdx.y * 128;
    if (m0 >= M) return;
    const int n0 = blockIdx.x * 128;

    extern __shared__ __half smh[];
    const __half* __restrict__ A = g.A;
    const __half* __restrict__ Wt = g.W;
    const int tid  = threadIdx.x;
    const int warp = tid >> 5, lane = tid & 31;
    const int gid  = lane >> 2, tig = lane & 3;
    const int wm = (warp & 3) * 32;
    const int wn = (warp >> 2) * 64;
    // ldmatrix lane->row mappings
    const int la  = lane & 7;
    const int lg1 = (lane >> 3) & 1;     // second 8-lane group bit
    const int lg2 = lane >> 4;           // upper-half bit

    const int nIters = K / 64;

    auto issue_tile = [&](int it, int stage) {
        __half* As = smh + stage * HSTAGE;
        __half* Bs = As + 128 * PH;
        const int k0 = it * 64;
        #pragma unroll
        for (int i = 0; i < 4; i++) {
            int c = tid + i * 256;
            int r = c >> 3, off = (c & 7) * 8;
            uint32_t dst = (uint32_t)__cvta_generic_to_shared(&As[r * PH + off]);
            const __half* src = &A[(size_t)(m0 + r) * K + k0 + off];
            CPA16(dst, src, (m0 + r < M) ? 16 : 0);
        }
        #pragma unroll
        for (int i = 0; i < 4; i++) {
            int c = tid + i * 256;
            int r = c >> 3, off = (c & 7) * 8;
            uint32_t dst = (uint32_t)__cvta_generic_to_shared(&Bs[r * PH + off]);
            const __half* src = &Wt[(size_t)(n0 + r) * K + k0 + off];
            CPA16(dst, src, 16);
        }
        CPCOMMIT();
    };

    float4 acc[2][8];
    #pragma unroll
    for (int i = 0; i < 2; i++)
        #pragma unroll
        for (int j = 0; j < 8; j++) acc[i][j] = make_float4(0.f, 0.f, 0.f, 0.f);

    issue_tile(0, 0);
    if (nIters > 1) issue_tile(1, 1);

    for (int it = 0; it < nIters; it++) {
        if (it + 1 < nIters) { CPWAIT(1); } else { CPWAIT(0); }
        __syncthreads();
        if (it + 2 < nIters) issue_tile(it + 2, (it + 2) % 3);

        const __half* As = smh + (it % 3) * HSTAGE;
        const __half* Bs = As + 128 * PH;
        // ldmatrix base addresses (per-lane row pointers), +32B per ks step
        uint32_t aaddr[2], baddr[4];
        #pragma unroll
        for (int mt = 0; mt < 2; mt++)
            aaddr[mt] = (uint32_t)__cvta_generic_to_shared(
                &As[(wm + mt * 16 + la + lg1 * 8) * PH + lg2 * 8]);
        #pragma unroll
        for (int j = 0; j < 4; j++)
            baddr[j] = (uint32_t)__cvta_generic_to_shared(
                &Bs[(wn + j * 16 + la + lg2 * 8) * PH + lg1 * 8]);

        #pragma unroll
        for (int ks = 0; ks < 4; ks++) {
            uint32_t af[2][4];
            #pragma unroll
            for (int mt = 0; mt < 2; mt++)
                ldmx4(af[mt][0], af[mt][1], af[mt][2], af[mt][3],
                      aaddr[mt] + ks * 32);
            uint32_t bf[8][2];
            #pragma unroll
            for (int j = 0; j < 4; j++)
                ldmx4(bf[2 * j][0], bf[2 * j][1], bf[2 * j + 1][0],
                      bf[2 * j + 1][1], baddr[j] + ks * 32);
            #pragma unroll
            for (int mt = 0; mt < 2; mt++)
                #pragma unroll
                for (int nt = 0; nt < 8; nt++)
                    mma_h16(acc[mt][nt], af[mt], bf[nt]);
        }
    }

    const float* bias = g.bias;
    float* C = g.C;
    #pragma unroll
    for (int mt = 0; mt < 2; mt++) {
        int r0 = m0 + wm + mt * 16 + gid;
        #pragma unroll
        for (int nt = 0; nt < 8; nt++) {
            int col = n0 + wn + nt * 8 + tig * 2;
            float b0 = bias ? bias[col] : 0.f;
            float b1 = bias ? bias[col + 1] : 0.f;
            if (r0 < M)
                *(float2*)&C[(size_t)r0 * DM + col] =
                    make_float2(acc[mt][nt].x + b0, acc[mt][nt].y + b1);
            if (r0 + 8 < M)
                *(float2*)&C[(size_t)(r0 + 8) * DM + col] =
                    make_float2(acc[mt][nt].z + b0, acc[mt][nt].w + b1);
        }
    }
}

// ------------- RMSNorm + RoPE -> fp16 [H, S_TOT, HD] ----------------------------
// q is additionally pre-scaled by SM_SCALE.
__global__ __launch_bounds__(128) void qkv_transform(
    const float* __restrict__ nqw, const float* __restrict__ nkw,
    const float* __restrict__ naqw, const float* __restrict__ nakw,
    const float* __restrict__ fcos, const float* __restrict__ fsin)
{
    const int s = blockIdx.x, h = blockIdx.y, d = threadIdx.x;
    const int lane = d & 31, wid = d >> 5;
    __shared__ float ws[4];
    const bool txt = s < S_TXT;
    const size_t roff = txt ? (size_t)s * DM : (size_t)(s - S_TXT) * DM;
    const size_t col = roff + h * HD + d;
    const float* xq = txt ? g_pq_txt : g_pq_img;
    const float* xk = txt ? g_pk_txt : g_pk_img;
    const float* xv = txt ? g_pv_txt : g_pv_img;
    const float wq = txt ? naqw[d] : nqw[d];
    const float wk = txt ? nakw[d] : nkw[d];
    const float c = fcos[s * HD + d];
    const float sn = fsin[s * HD + d];
    const size_t oidx = ((size_t)h * S_TOT + s) * HD + d;

    float q = xq[col];
    float t2 = q * q;
    #pragma unroll
    for (int off = 16; off; off >>= 1) t2 += __shfl_xor_sync(0xffffffffu, t2, off);
    if (lane == 0) ws[wid] = t2;
    __syncthreads();
    float tot = ws[0] + ws[1] + ws[2] + ws[3];
    float qn = q * rsqrtf(tot * (1.f / HD) + 1e-6f) * wq;
    float pq = __shfl_xor_sync(0xffffffffu, qn, 1);
    float rotq = (d & 1) ? pq : -pq;
    g_q[oidx] = __float2half((qn * c + rotq * sn) * SM_SCALE);
    __syncthreads();

    float k = xk[col];
    t2 = k * k;
    #pragma unroll
    for (int off = 16; off; off >>= 1) t2 += __shfl_xor_sync(0xffffffffu, t2, off);
    if (lane == 0) ws[wid] = t2;
    __syncthreads();
    tot = ws[0] + ws[1] + ws[2] + ws[3];
    float kn = k * rsqrtf(tot * (1.f / HD) + 1e-6f) * wk;
    float pk = __shfl_xor_sync(0xffffffffu, kn, 1);
    float rotk = (d & 1) ? pk : -pk;
    g_k[oidx] = __float2half(kn * c + rotk * sn);

    g_v[oidx] = __float2half(xv[col]);
}

// ---------------- fp16 tensor-core flash attention, cp.async double-buffered -----
// Fused epilogue: adapter 4-key cross-attention + merge -> writes g_hs (half).
#define AQ 128
#define AKV 64
#define QP 136               /* Q/K row pitch (halves); 68 words ≡ 4 mod 32 */
#define VP 72                /* Vt row pitch (halves); 36 words ≡ 4 mod 32 */
#define HOFF_Q 0
#define HOFF_K(st) (AQ * QP + (st) * (AKV * QP))
#define HOFF_V(st) (AQ * QP + 2 * (AKV * QP) + (st) * (HD * VP))
#define ATTN_SMEM ((AQ * QP + 2 * AKV * QP + 2 * HD * VP) * 2)

__global__ __launch_bounds__(256) void attn_mma(const float* __restrict__ bscale)
{
    extern __shared__ __half smah[];
    const int qt = blockIdx.x, h = blockIdx.y;
    const int tid = threadIdx.x;
    const int warp = tid >> 5, lane = tid & 31;
    const int gid = lane >> 2, tig = lane & 3;
    const int wm = warp * 16;

    const __half* Qg = g_q + ((size_t)h * S_TOT + qt * AQ) * HD;
    const __half* Kg = g_k + (size_t)h * S_TOT * HD;
    const __half* Vtg = g_vt + (size_t)h * HD * S_TOT;

    auto issue_kv = [&](int kt, int st) {
        __half* Ks = smah + HOFF_K(st);
        __half* Vs = smah + HOFF_V(st);
        const __half* Kt = Kg + (size_t)kt * AKV * HD;
        #pragma unroll
        for (int i = 0; i < 4; i++) {
            int c = tid + i * 256;
            int r = c >> 4, col = (c & 15) * 8;
            uint32_t dk = (uint32_t)__cvta_generic_to_shared(&Ks[r * QP + col]);
            CPA16(dk, &Kt[(size_t)r * HD + col], 16);
        }
        #pragma unroll
        for (int i = 0; i < 4; i++) {
            int c = tid + i * 256;
            int r = c >> 3, col = (c & 7) * 8;
            uint32_t dv = (uint32_t)__cvta_generic_to_shared(&Vs[r * VP + col]);
            CPA16(dv, &Vtg[(size_t)r * S_TOT + kt * AKV + col], 16);
        }
    };

    {
        #pragma unroll
        for (int i = 0; i < 8; i++) {
            int c = tid + i * 256;
            int r = c >> 4, col = (c & 15) * 8;
            uint32_t dq = (uint32_t)__cvta_generic_to_shared(&smah[r * QP + col]);
            CPA16(dq, &Qg[(size_t)r * HD + col], 16);
        }
        issue_kv(0, 0);
        CPCOMMIT();
    }

    float m0 = -1e30f, m1 = -1e30f, l0 = 0.f, l1 = 0.f;
    float4 o[16];
    #pragma unroll
    for (int i = 0; i < 16; i++) o[i] = make_float4(0.f, 0.f, 0.f, 0.f);

    const uint32_t* Qw = (const uint32_t*)smah;
    for (int kt = 0; kt < S_TOT / AKV; kt++) {
        const int st = kt & 1;
        CPWAIT(0);
        __syncthreads();
        if (kt + 1 < S_TOT / AKV) { issue_kv(kt + 1, st ^ 1); CPCOMMIT(); }

        const uint32_t* Kw = (const uint32_t*)(smah + HOFF_K(st));
        const uint32_t* Vw = (const uint32_t*)(smah + HOFF_V(st));

        float4 s[8];
        #pragma unroll
        for (int nb = 0; nb < 8; nb++) s[nb] = make_float4(0.f, 0.f, 0.f, 0.f);
        #pragma unroll
        for (int ks = 0; ks < HD / 16; ks++) {
            uint32_t a[4];
            int qb = (wm + gid) * 68 + ks * 8 + tig;
            a[0] = Qw[qb];
            a[1] = Qw[qb + 8 * 68];
            a[2] = Qw[qb + 4];
            a[3] = Qw[qb + 8 * 68 + 4];
            #pragma unroll
            for (int nb = 0; nb < 8; nb++) {
                uint32_t b[2];
                int kb = (nb * 8 + gid) * 68 + ks * 8 + tig;
                b[0] = Kw[kb];
                b[1] = Kw[kb + 4];
                mma_h16(s[nb], a, b);
            }
        }

        float mx0 = m0, mx1 = m1;
        #pragma unroll
        for (int nb = 0; nb < 8; nb++) {
            mx0 = fmaxf(mx0, fmaxf(s[nb].x, s[nb].y));
            mx1 = fmaxf(mx1, fmaxf(s[nb].z, s[nb].w));
        }
        mx0 = fmaxf(mx0, __shfl_xor_sync(0xffffffffu, mx0, 1));
        mx0 = fmaxf(mx0, __shfl_xor_sync(0xffffffffu, mx0, 2));
        mx1 = fmaxf(mx1, __shfl_xor_sync(0xffffffffu, mx1, 1));
        mx1 = fmaxf(mx1, __shfl_xor_sync(0xffffffffu, mx1, 2));
        const float c0 = __expf(m0 - mx0);
        const float c1 = __expf(m1 - mx1);
        m0 = mx0; m1 = mx1;
        float ls0 = 0.f, ls1 = 0.f;
        #pragma unroll
        for (int nb = 0; nb < 8; nb++) {
            s[nb].x = __expf(s[nb].x - m0);
            s[nb].y = __expf(s[nb].y - m0);
            s[nb].z = __expf(s[nb].z - m1);
            s[nb].w = __expf(s[nb].w - m1);
            ls0 += s[nb].x + s[nb].y;
            ls1 += s[nb].z + s[nb].w;
        }
        l0 = l0 * c0 + ls0;
        l1 = l1 * c1 + ls1;
        #pragma unroll
        for (int i = 0; i < 16; i++) {
            o[i].x *= c0; o[i].y *= c0; o[i].z *= c1; o[i].w *= c1;
        }

        #pragma unroll
        for (int ks = 0; ks < 4; ks++) {
            uint32_t a[4];
            a[0] = packh2(s[2 * ks].x,     s[2 * ks].y);
            a[1] = packh2(s[2 * ks].z,     s[2 * ks].w);
            a[2] = packh2(s[2 * ks + 1].x, s[2 * ks + 1].y);
            a[3] = packh2(s[2 * ks + 1].z, s[2 * ks + 1].w);
            #pragma unroll
            for (int nb = 0; nb < 16; nb++) {
                uint32_t b[2];
                int vb = (nb * 8 + gid) * 36 + ks * 8 + tig;
                b[0] = Vw[vb];
                b[1] = Vw[vb + 4];
                mma_h16(o[nb], a, b);
            }
        }
    }

    l0 += __shfl_xor_sync(0xffffffffu, l0, 1);
    l0 += __shfl_xor_sync(0xffffffffu, l0, 2);
    l1 += __shfl_xor_sync(0xffffffffu, l1, 1);
    l1 += __shfl_xor_sync(0xffffffffu, l1, 2);
    const float i0 = 1.f / l0, i1 = 1.f / l1;

    // ---- fused adapter cross-attention (Qs resident in smem; pre-scaled q) ----
    const int lr0 = wm + gid, lr1 = lr0 + 8;
    float sc0[ATOK], sc1[ATOK];
    #pragma unroll
    for (int t = 0; t < ATOK; t++) {
        const float* kap = &g_ka[t * DM + h * HD];
        float a0 = 0.f, a1 = 0.f;
        #pragma unroll
        for (int nb = 0; nb < 16; nb++) {
            int cc = nb * 8 + tig * 2;
            float k0v = kap[cc], k1v = kap[cc + 1];
            float2 q0 = __half22float2(*(const __half2*)&smah[lr0 * QP + cc]);
            float2 q1 = __half22float2(*(const __half2*)&smah[lr1 * QP + cc]);
            a0 += q0.x * k0v + q0.y * k1v;
            a1 += q1.x * k0v + q1.y * k1v;
        }
        a0 += __shfl_xor_sync(0xffffffffu, a0, 1);
        a0 += __shfl_xor_sync(0xffffffffu, a0, 2);
        a1 += __shfl_xor_sync(0xffffffffu, a1, 1);
        a1 += __shfl_xor_sync(0xffffffffu, a1, 2);
        sc0[t] = a0; sc1[t] = a1;
    }
    float w0[ATOK], w1[ATOK];
    {
        float mxa = fmaxf(fmaxf(sc0[0], sc0[1]), fmaxf(sc0[2], sc0[3]));
        float e0 = __expf(sc0[0] - mxa), e1 = __expf(sc0[1] - mxa);
        float e2 = __expf(sc0[2] - mxa), e3 = __expf(sc0[3] - mxa);
        float inv = 1.f / (e0 + e1 + e2 + e3);
        w0[0] = e0 * inv; w0[1] = e1 * inv; w0[2] = e2 * inv; w0[3] = e3 * inv;
    }
    {
        float mxa = fmaxf(fmaxf(sc1[0], sc1[1]), fmaxf(sc1[2], sc1[3]));
        float e0 = __expf(sc1[0] - mxa), e1 = __expf(sc1[1] - mxa);
        float e2 = __expf(sc1[2] - mxa), e3 = __expf(sc1[3] - mxa);
        float inv = 1.f / (e0 + e1 + e2 + e3);
        w1[0] = e0 * inv; w1[1] = e1 * inv; w1[2] = e2 * inv; w1[3] = e3 * inv;
    }
    const float bsc = bscale[0];

    const int s0 = qt * AQ + lr0;
    __half* H0 = g_hs + (size_t)s0 * DM + h * HD;
    __half* H1 = H0 + 8 * DM;
    #pragma unroll
    for (int nb = 0; nb < 16; nb++) {
        int cc = nb * 8 + tig * 2;
        int hcol = h * HD + cc;
        float va0a = g_va[0 * DM + hcol], va0b = g_va[0 * DM + hcol + 1];
        float va1a = g_va[1 * DM + hcol], va1b = g_va[1 * DM + hcol + 1];
        float va2a = g_va[2 * DM + hcol], va2b = g_va[2 * DM + hcol + 1];
        float va3a = g_va[3 * DM + hcol], va3b = g_va[3 * DM + hcol + 1];
        float vd0a = w0[0] * va0a + w0[1] * va1a + w0[2] * va2a + w0[3] * va3a;
        float vd0b = w0[0] * va0b + w0[1] * va1b + w0[2] * va2b + w0[3] * va3b;
        float vd1a = w1[0] * va0a + w1[1] * va1a + w1[2] * va2a + w1[3] * va3a;
        float vd1b = w1[0] * va0b + w1[1] * va1b + w1[2] * va2b + w1[3] * va3b;
        *(__half2*)&H0[cc] = __floats2half2_rn(o[nb].x * i0 + bsc * vd0a,
                                               o[nb].y * i0 + bsc * vd0b);
        *(__half2*)&H1[cc] = __floats2half2_rn(o[nb].z * i1 + bsc * vd1a,
                                               o[nb].w * i1 + bsc * vd1b);
    }
}

// -------------------------------- launch ---------------------------------------
extern "C" void kernel_launch(void* const* d_in, const int* in_sizes, int n_in,
                              void* d_out, int out_size)
{
    const float* hidden = (const float*)d_in[0];
    const float* enc    = (const float*)d_in[1];
    const float* adapt  = (const float*)d_in[2];
    const float* fcos   = (const float*)d_in[3];
    const float* fsin   = (const float*)d_in[4];
    const float* Wq  = (const float*)d_in[5];  const float* bq  = (const float*)d_in[6];
    const float* Wk  = (const float*)d_in[7];  const float* bk  = (const float*)d_in[8];
    const float* Wv  = (const float*)d_in[9];  const float* bv  = (const float*)d_in[10];
    const float* nqw = (const float*)d_in[11]; const float* nkw = (const float*)d_in[12];
    const float* Wqa = (const float*)d_in[13]; const float* bqa = (const float*)d_in[14];
    const float* Wka = (const float*)d_in[15]; const float* bka = (const float*)d_in[16];
    const float* Wva = (const float*)d_in[17]; const float* bva = (const float*)d_in[18];
    const float* naqw = (const float*)d_in[19]; const float* nakw = (const float*)d_in[20];
    const float* Wo  = (const float*)d_in[21]; const float* bo  = (const float*)d_in[22];
    const float* Woa = (const float*)d_in[23]; const float* boa = (const float*)d_in[24];
    const float* Wkad = (const float*)d_in[25]; const float* Wvad = (const float*)d_in[26];
    const float* bscale = (const float*)d_in[27];
    float* out = (float*)d_out;

    float *pq_img, *pk_img, *pv_img, *pq_txt, *pk_txt, *pv_txt, *ka, *va;
    __half *hs, *chid, *cenc, *cad, *cWq, *cWk, *cWv, *cWqa, *cWka, *cWva,
           *cWo, *cWoa, *cWkad, *cWvad;
    cudaGetSymbolAddress((void**)&pq_img, g_pq_img);
    cudaGetSymbolAddress((void**)&pk_img, g_pk_img);
    cudaGetSymbolAddress((void**)&pv_img, g_pv_img);
    cudaGetSymbolAddress((void**)&pq_txt, g_pq_txt);
    cudaGetSymbolAddress((void**)&pk_txt, g_pk_txt);
    cudaGetSymbolAddress((void**)&pv_txt, g_pv_txt);
    cudaGetSymbolAddress((void**)&ka, g_ka);
    cudaGetSymbolAddress((void**)&va, g_va);
    cudaGetSymbolAddress((void**)&hs, g_hs);
    cudaGetSymbolAddress((void**)&chid, g_chid);
    cudaGetSymbolAddress((void**)&cenc, g_cenc);
    cudaGetSymbolAddress((void**)&cad, g_cad);
    cudaGetSymbolAddress((void**)&cWq, g_cWq);
    cudaGetSymbolAddress((void**)&cWk, g_cWk);
    cudaGetSymbolAddress((void**)&cWv, g_cWv);
    cudaGetSymbolAddress((void**)&cWqa, g_cWqa);
    cudaGetSymbolAddress((void**)&cWka, g_cWka);
    cudaGetSymbolAddress((void**)&cWva, g_cWva);
    cudaGetSymbolAddress((void**)&cWo, g_cWo);
    cudaGetSymbolAddress((void**)&cWoa, g_cWoa);
    cudaGetSymbolAddress((void**)&cWkad, g_cWkad);
    cudaGetSymbolAddress((void**)&cWvad, g_cWvad);

    cudaFuncSetAttribute(attn_mma, cudaFuncAttributeMaxDynamicSharedMemorySize,
                         ATTN_SMEM);
    cudaFuncSetAttribute(gemm_h, cudaFuncAttributeMaxDynamicSharedMemorySize,
                         HSMEM);

    // --- convert activations to half; transpose+convert weights ---
    CVH3 cv;
    cv.e[0] = { hidden, chid, S_IMG * DM };
    cv.e[1] = { enc,    cenc, S_TXT * DM };
    cv.e[2] = { adapt,  cad,  ATOK * ADIM };
    prep_cvt<<<dim3((S_IMG * DM + 1023) / 1024, 3), 256>>>(cv);

    TP10 tp;
    tp.e[0] = { Wq,   cWq,   DM };
    tp.e[1] = { Wk,   cWk,   DM };
    tp.e[2] = { Wv,   cWv,   DM };
    tp.e[3] = { Wqa,  cWqa,  DM };
    tp.e[4] = { Wka,  cWka,  DM };
    tp.e[5] = { Wva,  cWva,  DM };
    tp.e[6] = { Wo,   cWo,   DM };
    tp.e[7] = { Woa,  cWoa,  DM };
    tp.e[8] = { Wkad, cWkad, ADIM };
    tp.e[9] = { Wvad, cWvad, ADIM };
    prep_tp<<<dim3(DM / 32, DM / 32, 10), 256>>>(tp);

    // --- all 6 QKV projections in one launch ---
    GB6 qkv;
    qkv.e[0] = { chid, cWq,  bq,  pq_img, S_IMG, DM };
    qkv.e[1] = { chid, cWk,  bk,  pk_img, S_IMG, DM };
    qkv.e[2] = { chid, cWv,  bv,  pv_img, S_IMG, DM };
    qkv.e[3] = { cenc, cWqa, bqa, pq_txt, S_TXT, DM };
    qkv.e[4] = { cenc, cWka, bka, pk_txt, S_TXT, DM };
    qkv.e[5] = { cenc, cWva, bva, pv_txt, S_TXT, DM };
    gemm_h<<<dim3(DM / 128, S_IMG / 128, 6), 256, HSMEM>>>(qkv);

    // --- adapter K/V (M=4, K=1024) ---
    GB6 ad;
    ad.e[0] = { cad, cWkad, (const float*)0, ka, ATOK, ADIM };
    ad.e[1] = { cad, cWvad, (const float*)0, va, ATOK, ADIM };
    ad.e[2] = ad.e[0]; ad.e[3] = ad.e[0]; ad.e[4] = ad.e[0]; ad.e[5] = ad.e[0];
    gemm_h<<<dim3(DM / 128, 1, 2), 256, HSMEM>>>(ad);

    // RMSNorm + RoPE + head layout (fp16 out, q pre-scaled)
    qkv_transform<<<dim3(S_TOT, NH), 128>>>(nqw, nkw, naqw, nakw, fcos, fsin);
    // V transpose for fp16 PV mma
    vtp<<<dim3(S_TOT / 32, HD / 32, NH), 256>>>();
    // joint flash attention + fused adapter merge -> g_hs (half)
    attn_mma<<<dim3(S_TOT / AQ, NH), 256, ATTN_SMEM>>>(bscale);

    // --- both output projections in one launch ---
    GB6 op;
    op.e[0] = { hs + (size_t)S_TXT * DM, cWo,  bo,  out,                      S_IMG, DM };
    op.e[1] = { hs,                      cWoa, boa, out + (size_t)S_IMG * DM, S_TXT, DM };
    op.e[2] = op.e[0]; op.e[3] = op.e[0]; op.e[4] = op.e[0]; op.e[5] = op.e[0];
    gemm_h<<<dim3(DM / 128, S_IMG / 128, 2), 256, HSMEM>>>(op);
}